// round 1
// baseline (speedup 1.0000x reference)
#include <cuda_runtime.h>

#define BB 16
#define HH 96
#define WW 128
#define HWP (HH*WW)        // 12288
#define CP 196
#define C1 96
#define CF1 64
#define CF2 32
#define CM 128
#define CO 80
#define OUTC 82

// ---- scratch + quantized weights (device globals: no allocation allowed) ----
__device__ float g_corflo[(size_t)BB*CM*HWP];   // [B,128,H,W] ~100MB
__device__ float g_Wc1t[CP*C1];                 // transposed [196][96]
__device__ float g_Wf1[CF1*2];
__device__ float g_Wf2[CF2*CF1];
__device__ float g_Wd[CM*9];
__device__ float g_Wpt[CM*CO];                  // transposed [128][80]

// ---------------------------------------------------------------------------
// Per-tensor symmetric int8 fake-quant: scale = max(|w|,1e-8)/127,
// q = clip(rint(w/scale), +-127)*scale.  rintf = round-half-even = jnp.round.
// One block per tensor.
// ---------------------------------------------------------------------------
__global__ void quant_kernel(const float* __restrict__ Wc1,
                             const float* __restrict__ Wf1,
                             const float* __restrict__ Wf2,
                             const float* __restrict__ Wd,
                             const float* __restrict__ Wp) {
    __shared__ float smax[256];
    __shared__ float sscale;
    int t = blockIdx.x;
    const float* src; int n;
    if (t == 0)      { src = Wc1; n = C1*CP;   }
    else if (t == 1) { src = Wf1; n = CF1*2;   }
    else if (t == 2) { src = Wf2; n = CF2*CF1; }
    else if (t == 3) { src = Wd;  n = CM*9;    }
    else             { src = Wp;  n = CO*CM;   }

    float m = 0.f;
    for (int i = threadIdx.x; i < n; i += 256) m = fmaxf(m, fabsf(src[i]));
    smax[threadIdx.x] = m;
    __syncthreads();
    for (int s = 128; s > 0; s >>= 1) {
        if (threadIdx.x < s)
            smax[threadIdx.x] = fmaxf(smax[threadIdx.x], smax[threadIdx.x + s]);
        __syncthreads();
    }
    if (threadIdx.x == 0) sscale = fmaxf(smax[0], 1e-8f) / 127.f;
    __syncthreads();
    float sc = sscale, inv = 1.f / sc;

    for (int i = threadIdx.x; i < n; i += 256) {
        float q = rintf(src[i] * inv);
        q = fminf(fmaxf(q, -127.f), 127.f) * sc;
        if (t == 0)      { int oc = i / CP, k = i % CP; g_Wc1t[k*C1 + oc] = q; }
        else if (t == 1) g_Wf1[i] = q;
        else if (t == 2) g_Wf2[i] = q;
        else if (t == 3) g_Wd[i]  = q;
        else             { int o = i / CM, k = i % CM; g_Wpt[k*CO + o] = q; }
    }
}

// ---------------------------------------------------------------------------
// Flow MLP 2->64->32 (relu), writes cor_flo channels [96,128); also copies
// flow passthrough into out channels 80,81.
// ---------------------------------------------------------------------------
__global__ void flo_kernel(const float* __restrict__ flow,
                           const float* __restrict__ bf1,
                           const float* __restrict__ bf2,
                           float* __restrict__ out) {
    __shared__ float sW1[CF1*2], sb1[CF1], sW2[CF2*CF1], sb2[CF2];
    int tid = threadIdx.x;
    for (int i = tid; i < CF1*2;   i += 256) sW1[i] = g_Wf1[i];
    for (int i = tid; i < CF1;     i += 256) sb1[i] = bf1[i];
    for (int i = tid; i < CF2*CF1; i += 256) sW2[i] = g_Wf2[i];
    for (int i = tid; i < CF2;     i += 256) sb2[i] = bf2[i];
    __syncthreads();

    int gid = blockIdx.x * 256 + tid;        // 0 .. B*HW-1
    int b = gid / HWP, px = gid % HWP;
    float f0 = flow[((size_t)b*2 + 0)*HWP + px];
    float f1 = flow[((size_t)b*2 + 1)*HWP + px];

    float hid[CF1];
#pragma unroll
    for (int h = 0; h < CF1; h++)
        hid[h] = fmaxf(f0*sW1[h*2] + f1*sW1[h*2+1] + sb1[h], 0.f);

#pragma unroll
    for (int o = 0; o < CF2; o++) {
        float a = sb2[o];
#pragma unroll
        for (int h = 0; h < CF1; h++) a += hid[h] * sW2[o*CF1 + h];
        g_corflo[((size_t)(b*CM + C1 + o))*HWP + px] = fmaxf(a, 0.f);
    }
    out[((size_t)(b*OUTC + 80))*HWP + px] = f0;
    out[((size_t)(b*OUTC + 81))*HWP + px] = f1;
}

// ---------------------------------------------------------------------------
// Big 1x1 conv as GEMM: cor[96, HW] = Wc1q[96,196] @ corr[196, HW] per batch.
// Block = 96 oc x 128 px, K chunks of 28. Thread micro-tile 6 oc x 8 px,
// strided (ocg+16i, pxg+16j) for conflict-free / broadcast smem reads.
// ---------------------------------------------------------------------------
#define KC1 28
__global__ void conv1_kernel(const float* __restrict__ corr,
                             const float* __restrict__ bc1) {
    __shared__ float Xs[KC1][WW];     // 28 x 128
    __shared__ float Wsm[KC1][C1];    // 28 x 96
    int tid  = threadIdx.x;
    int b    = blockIdx.y;
    int px0  = blockIdx.x * WW;
    int ocg  = tid >> 4;              // 0..15
    int pxg  = tid & 15;              // 0..15

    float acc[6][8];
#pragma unroll
    for (int i = 0; i < 6; i++)
#pragma unroll
        for (int j = 0; j < 8; j++) acc[i][j] = 0.f;

    for (int k0 = 0; k0 < CP; k0 += KC1) {
        for (int i = tid; i < KC1*WW; i += 256) {
            int kk = i >> 7, p = i & 127;
            Xs[kk][p] = corr[((size_t)(b*CP + k0 + kk))*HWP + px0 + p];
        }
        for (int i = tid; i < KC1*C1; i += 256) {
            int kk = i / C1, oc = i % C1;
            Wsm[kk][oc] = g_Wc1t[(k0 + kk)*C1 + oc];
        }
        __syncthreads();
#pragma unroll 4
        for (int k = 0; k < KC1; k++) {
            float x[8], w[6];
#pragma unroll
            for (int j = 0; j < 8; j++) x[j] = Xs[k][pxg + 16*j];
#pragma unroll
            for (int i = 0; i < 6; i++) w[i] = Wsm[k][ocg + 16*i];
#pragma unroll
            for (int i = 0; i < 6; i++)
#pragma unroll
                for (int j = 0; j < 8; j++) acc[i][j] += w[i]*x[j];
        }
        __syncthreads();
    }
#pragma unroll
    for (int i = 0; i < 6; i++) {
        int oc = ocg + 16*i;
        float bias = bc1[oc];
#pragma unroll
        for (int j = 0; j < 8; j++)
            g_corflo[((size_t)(b*CM + oc))*HWP + px0 + pxg + 16*j] =
                fmaxf(acc[i][j] + bias, 0.f);
    }
}

// ---------------------------------------------------------------------------
// Fused depthwise 3x3 (pad=1, groups=128) + pointwise 128->80 + relu.
// Block = one (b, y, 64-px x-tile). Channels staged in chunks of 16:
// halo load -> dw into smem -> GEMM accumulate (5 oc x 4 px per thread).
// ---------------------------------------------------------------------------
#define PT 64
#define KC3 16
__global__ void dwpw_kernel(const float* __restrict__ bp,
                            float* __restrict__ out) {
    __shared__ float hs[KC3][3][68];    // halo rows, 66 used
    __shared__ float dws[KC3][PT];
    __shared__ float wps[KC3][CO];
    __shared__ float wds[KC3][12];      // 9 used
    int tid = threadIdx.x;
    int x0  = blockIdx.x * PT;
    int y   = blockIdx.y;
    int b   = blockIdx.z;
    int ocg = tid & 15;                 // 0..15
    int pxg = tid >> 4;                 // 0..15

    float acc[5][4];
#pragma unroll
    for (int i = 0; i < 5; i++)
#pragma unroll
        for (int j = 0; j < 4; j++) acc[i][j] = 0.f;

    for (int k0 = 0; k0 < CM; k0 += KC3) {
        __syncthreads();   // protect smem reuse from previous chunk's reads
        for (int i = tid; i < KC3*3*66; i += 256) {
            int cc = i / 198, r = (i / 66) % 3, xx = i % 66;
            int gy = y - 1 + r, gx = x0 - 1 + xx;
            float v = 0.f;
            if ((unsigned)gy < HH && (unsigned)gx < WW)
                v = g_corflo[((size_t)(b*CM + k0 + cc))*HWP + gy*WW + gx];
            hs[cc][r][xx] = v;
        }
        for (int i = tid; i < KC3*9; i += 256)
            wds[i/9][i%9] = g_Wd[(k0 + i/9)*9 + (i%9)];
        for (int i = tid; i < KC3*CO; i += 256)
            wps[i/CO][i%CO] = g_Wpt[(k0 + i/CO)*CO + (i%CO)];
        __syncthreads();

        // depthwise: 16 ch x 64 px, 4 values per thread
#pragma unroll
        for (int t = 0; t < 4; t++) {
            int v  = tid + 256*t;
            int cc = v >> 6, px = v & 63;
            float a = 0.f;
#pragma unroll
            for (int r = 0; r < 3; r++)
#pragma unroll
                for (int dx = 0; dx < 3; dx++)
                    a += hs[cc][r][px + dx] * wds[cc][r*3 + dx];
            dws[cc][px] = a;
        }
        __syncthreads();

        // pointwise GEMM accumulate
#pragma unroll
        for (int k = 0; k < KC3; k++) {
            float x[4], w[5];
#pragma unroll
            for (int j = 0; j < 4; j++) x[j] = dws[k][pxg + 16*j];
#pragma unroll
            for (int i = 0; i < 5; i++) w[i] = wps[k][ocg + 16*i];
#pragma unroll
            for (int i = 0; i < 5; i++)
#pragma unroll
                for (int j = 0; j < 4; j++) acc[i][j] += w[i]*x[j];
        }
    }
#pragma unroll
    for (int i = 0; i < 5; i++) {
        int o = ocg + 16*i;
        float bias = bp[o];
#pragma unroll
        for (int j = 0; j < 4; j++)
            out[((size_t)(b*OUTC + o))*HWP + y*WW + x0 + pxg + 16*j] =
                fmaxf(acc[i][j] + bias, 0.f);
    }
}

// ---------------------------------------------------------------------------
extern "C" void kernel_launch(void* const* d_in, const int* in_sizes, int n_in,
                              void* d_out, int out_size) {
    const float* flow = (const float*)d_in[0];
    const float* corr = (const float*)d_in[1];
    const float* Wc1  = (const float*)d_in[2];
    const float* bc1  = (const float*)d_in[3];
    const float* Wf1  = (const float*)d_in[4];
    const float* bf1  = (const float*)d_in[5];
    const float* Wf2  = (const float*)d_in[6];
    const float* bf2  = (const float*)d_in[7];
    const float* Wd   = (const float*)d_in[8];
    const float* Wp   = (const float*)d_in[9];
    const float* bp   = (const float*)d_in[10];
    float* out = (float*)d_out;

    quant_kernel<<<5, 256>>>(Wc1, Wf1, Wf2, Wd, Wp);
    flo_kernel<<<(BB*HWP)/256, 256>>>(flow, bf1, bf2, out);
    conv1_kernel<<<dim3(HWP/WW, BB), 256>>>(corr, bc1);
    dwpw_kernel<<<dim3(WW/PT, HH, BB), 256>>>(bp, out);
}

// round 2
// speedup vs baseline: 1.8469x; 1.8469x over previous
#include <cuda_runtime.h>

#define BB 16
#define HH 96
#define WW 128
#define HWP (HH*WW)        // 12288
#define CP 196
#define C1 96
#define CF1 64
#define CF2 32
#define CM 128
#define CO 80
#define OUTC 82

typedef unsigned long long ull;

// ---- scratch + quantized weights (device globals: no allocation allowed) ----
__device__ float g_corflo[(size_t)BB*CM*HWP];   // [B,128,H,W] ~100MB
__device__ float g_dw[(size_t)BB*CM*HWP];       // depthwise result ~100MB
__device__ float g_Wc1t[CP*C1];                 // transposed [196][96]
__device__ float g_Wf1[CF1*2];
__device__ float g_Wf2[CF2*CF1];
__device__ float g_Wd[CM*9];
__device__ float g_Wpt[CM*CO];                  // transposed [128][80]

// ---- packed f32x2 helpers (FFMA2 path; ptxas only emits via PTX) ----------
__device__ __forceinline__ void ffma2(ull &d, ull a, ull b) {
    asm("fma.rn.f32x2 %0, %1, %2, %0;" : "+l"(d) : "l"(a), "l"(b));
}
__device__ __forceinline__ ull dup2(float w) {
    ull r; asm("mov.b64 %0, {%1, %1};" : "=l"(r) : "f"(w)); return r;
}
__device__ __forceinline__ void unpack2(float &lo, float &hi, ull v) {
    asm("mov.b64 {%0, %1}, %2;" : "=f"(lo), "=f"(hi) : "l"(v));
}

// ---------------------------------------------------------------------------
// Per-tensor symmetric int8 fake-quant. One block per tensor, 1024 threads.
// ---------------------------------------------------------------------------
__global__ void quant_kernel(const float* __restrict__ Wc1,
                             const float* __restrict__ Wf1,
                             const float* __restrict__ Wf2,
                             const float* __restrict__ Wd,
                             const float* __restrict__ Wp) {
    __shared__ float smax[1024];
    __shared__ float sscale;
    int t = blockIdx.x;
    const float* src; int n;
    if (t == 0)      { src = Wc1; n = C1*CP;   }
    else if (t == 1) { src = Wf1; n = CF1*2;   }
    else if (t == 2) { src = Wf2; n = CF2*CF1; }
    else if (t == 3) { src = Wd;  n = CM*9;    }
    else             { src = Wp;  n = CO*CM;   }

    float m = 0.f;
    for (int i = threadIdx.x; i < n; i += 1024) m = fmaxf(m, fabsf(src[i]));
    smax[threadIdx.x] = m;
    __syncthreads();
    for (int s = 512; s > 0; s >>= 1) {
        if (threadIdx.x < s)
            smax[threadIdx.x] = fmaxf(smax[threadIdx.x], smax[threadIdx.x + s]);
        __syncthreads();
    }
    if (threadIdx.x == 0) sscale = fmaxf(smax[0], 1e-8f) / 127.f;
    __syncthreads();
    float sc = sscale, inv = 1.f / sc;

    for (int i = threadIdx.x; i < n; i += 1024) {
        float q = rintf(src[i] * inv);
        q = fminf(fmaxf(q, -127.f), 127.f) * sc;
        if (t == 0)      { int oc = i / CP, k = i % CP; g_Wc1t[k*C1 + oc] = q; }
        else if (t == 1) g_Wf1[i] = q;
        else if (t == 2) g_Wf2[i] = q;
        else if (t == 3) g_Wd[i]  = q;
        else             { int o = i / CM, k = i % CM; g_Wpt[k*CO + o] = q; }
    }
}

// ---------------------------------------------------------------------------
// Flow MLP 2->64->32 (relu), writes cor_flo channels [96,128); also copies
// flow passthrough into out channels 80,81.
// ---------------------------------------------------------------------------
__global__ void flo_kernel(const float* __restrict__ flow,
                           const float* __restrict__ bf1,
                           const float* __restrict__ bf2,
                           float* __restrict__ out) {
    __shared__ float sW1[CF1*2], sb1[CF1], sW2[CF2*CF1], sb2[CF2];
    int tid = threadIdx.x;
    for (int i = tid; i < CF1*2;   i += 256) sW1[i] = g_Wf1[i];
    for (int i = tid; i < CF1;     i += 256) sb1[i] = bf1[i];
    for (int i = tid; i < CF2*CF1; i += 256) sW2[i] = g_Wf2[i];
    for (int i = tid; i < CF2;     i += 256) sb2[i] = bf2[i];
    __syncthreads();

    int gid = blockIdx.x * 256 + tid;
    int b = gid / HWP, px = gid % HWP;
    float f0 = flow[((size_t)b*2 + 0)*HWP + px];
    float f1 = flow[((size_t)b*2 + 1)*HWP + px];

    float hid[CF1];
#pragma unroll
    for (int h = 0; h < CF1; h++)
        hid[h] = fmaxf(f0*sW1[h*2] + f1*sW1[h*2+1] + sb1[h], 0.f);

#pragma unroll
    for (int o = 0; o < CF2; o++) {
        float a = sb2[o];
#pragma unroll
        for (int h = 0; h < CF1; h++) a += hid[h] * sW2[o*CF1 + h];
        g_corflo[((size_t)(b*CM + C1 + o))*HWP + px] = fmaxf(a, 0.f);
    }
    out[((size_t)(b*OUTC + 80))*HWP + px] = f0;
    out[((size_t)(b*OUTC + 81))*HWP + px] = f1;
}

// ---------------------------------------------------------------------------
// Big 1x1 conv GEMM with packed f32x2: cor[96,HW] = Wc1q[96,196] @ corr.
// Block = 96 oc x 128 px. Thread = 6 oc x 8 px (4 pixel-pairs).
// Pixel pair p = px0 + pxg*2 + 32*j (+1): LDS.64 x-reads, float2 stores.
// ---------------------------------------------------------------------------
#define KC1 28
__global__ void __launch_bounds__(256)
conv1_kernel(const float* __restrict__ corr, const float* __restrict__ bc1) {
    __shared__ float Xs[KC1][WW];     // 28 x 128 = 14KB
    __shared__ float Wsm[KC1][C1];    // 28 x 96  = 10.5KB
    int tid  = threadIdx.x;
    int b    = blockIdx.y;
    int px0  = blockIdx.x * WW;
    int ocg  = tid >> 4;              // 0..15
    int pxg  = tid & 15;              // 0..15

    ull acc[6][4];
#pragma unroll
    for (int i = 0; i < 6; i++)
#pragma unroll
        for (int j = 0; j < 4; j++) acc[i][j] = 0ull;

    for (int k0 = 0; k0 < CP; k0 += KC1) {
        // stage X: 896 float4
        for (int i = tid; i < KC1*WW/4; i += 256) {
            int kk = i >> 5, c4 = (i & 31) * 4;
            *(float4*)&Xs[kk][c4] =
                *(const float4*)&corr[((size_t)(b*CP + k0 + kk))*HWP + px0 + c4];
        }
        // stage W: chunk rows contiguous in g_Wc1t -> flat float4 copy
        for (int i = tid; i < KC1*C1/4; i += 256)
            ((float4*)Wsm)[i] = ((const float4*)(g_Wc1t + k0*C1))[i];
        __syncthreads();
#pragma unroll 2
        for (int k = 0; k < KC1; k++) {
            ull x2[4], w2[6];
#pragma unroll
            for (int j = 0; j < 4; j++)
                x2[j] = *(const ull*)&Xs[k][pxg*2 + 32*j];
#pragma unroll
            for (int i = 0; i < 6; i++) w2[i] = dup2(Wsm[k][ocg + 16*i]);
#pragma unroll
            for (int i = 0; i < 6; i++)
#pragma unroll
                for (int j = 0; j < 4; j++) ffma2(acc[i][j], w2[i], x2[j]);
        }
        __syncthreads();
    }
#pragma unroll
    for (int i = 0; i < 6; i++) {
        int oc = ocg + 16*i;
        float bias = bc1[oc];
#pragma unroll
        for (int j = 0; j < 4; j++) {
            float lo, hi; unpack2(lo, hi, acc[i][j]);
            float2 v = make_float2(fmaxf(lo + bias, 0.f), fmaxf(hi + bias, 0.f));
            *(float2*)&g_corflo[((size_t)(b*CM + oc))*HWP + px0 + pxg*2 + 32*j] = v;
        }
    }
}

// ---------------------------------------------------------------------------
// Depthwise 3x3 (pad=1): pure elementwise, float4 in/out, no smem GEMM.
// grid (HH/8, CM, BB); thread = 4 consecutive pixels of one (b,c,y).
// ---------------------------------------------------------------------------
__global__ void dw_kernel() {
    int c   = blockIdx.y, b = blockIdx.z;
    int sub = threadIdx.x >> 5;          // 0..7
    int xq  = (threadIdx.x & 31) * 4;    // 0..124
    int y   = blockIdx.x * 8 + sub;

    const float* base = g_corflo + ((size_t)(b*CM + c))*HWP + y*WW + xq;
    float w[9];
#pragma unroll
    for (int i = 0; i < 9; i++) w[i] = g_Wd[c*9 + i];

    float4 a = make_float4(0.f, 0.f, 0.f, 0.f);
#pragma unroll
    for (int r = 0; r < 3; r++) {
        int gy = y - 1 + r;
        if ((unsigned)gy >= HH) continue;
        const float* rp = base + (r-1)*WW;
        float4 f = *(const float4*)rp;
        float xl = (xq > 0)      ? rp[-1] : 0.f;
        float xr = (xq < WW - 4) ? rp[4]  : 0.f;
        float w0 = w[r*3], w1 = w[r*3+1], w2 = w[r*3+2];
        a.x += w0*xl  + w1*f.x + w2*f.y;
        a.y += w0*f.x + w1*f.y + w2*f.z;
        a.z += w0*f.y + w1*f.z + w2*f.w;
        a.w += w0*f.z + w1*f.w + w2*xr;
    }
    *(float4*)(g_dw + ((size_t)(b*CM + c))*HWP + y*WW + xq) = a;
}

// ---------------------------------------------------------------------------
// Pointwise 128->80 GEMM with packed f32x2 + bias + relu.
// Block = 80 oc x 128 px. Thread = 5 oc x 8 px (4 pixel-pairs).
// ---------------------------------------------------------------------------
#define KPW 32
__global__ void __launch_bounds__(256)
pw_kernel(const float* __restrict__ bp, float* __restrict__ out) {
    __shared__ float Xs[KPW][WW];     // 32 x 128 = 16KB
    __shared__ float Ws[KPW][CO];     // 32 x 80  = 10KB
    int tid  = threadIdx.x;
    int b    = blockIdx.y;
    int px0  = blockIdx.x * WW;
    int ocg  = tid >> 4;              // 0..15
    int pxg  = tid & 15;              // 0..15

    ull acc[5][4];
#pragma unroll
    for (int i = 0; i < 5; i++)
#pragma unroll
        for (int j = 0; j < 4; j++) acc[i][j] = 0ull;

    for (int k0 = 0; k0 < CM; k0 += KPW) {
        for (int i = tid; i < KPW*WW/4; i += 256) {
            int kk = i >> 5, c4 = (i & 31) * 4;
            *(float4*)&Xs[kk][c4] =
                *(const float4*)&g_dw[((size_t)(b*CM + k0 + kk))*HWP + px0 + c4];
        }
        for (int i = tid; i < KPW*CO/4; i += 256)
            ((float4*)Ws)[i] = ((const float4*)(g_Wpt + k0*CO))[i];
        __syncthreads();
#pragma unroll 2
        for (int k = 0; k < KPW; k++) {
            ull x2[4], w2[5];
#pragma unroll
            for (int j = 0; j < 4; j++)
                x2[j] = *(const ull*)&Xs[k][pxg*2 + 32*j];
#pragma unroll
            for (int i = 0; i < 5; i++) w2[i] = dup2(Ws[k][ocg + 16*i]);
#pragma unroll
            for (int i = 0; i < 5; i++)
#pragma unroll
                for (int j = 0; j < 4; j++) ffma2(acc[i][j], w2[i], x2[j]);
        }
        __syncthreads();
    }
#pragma unroll
    for (int i = 0; i < 5; i++) {
        int oc = ocg + 16*i;
        float bias = bp[oc];
#pragma unroll
        for (int j = 0; j < 4; j++) {
            float lo, hi; unpack2(lo, hi, acc[i][j]);
            float2 v = make_float2(fmaxf(lo + bias, 0.f), fmaxf(hi + bias, 0.f));
            *(float2*)&out[((size_t)(b*OUTC + oc))*HWP + px0 + pxg*2 + 32*j] = v;
        }
    }
}

// ---------------------------------------------------------------------------
extern "C" void kernel_launch(void* const* d_in, const int* in_sizes, int n_in,
                              void* d_out, int out_size) {
    const float* flow = (const float*)d_in[0];
    const float* corr = (const float*)d_in[1];
    const float* Wc1  = (const float*)d_in[2];
    const float* bc1  = (const float*)d_in[3];
    const float* bf1  = (const float*)d_in[5];
    const float* bf2  = (const float*)d_in[7];
    const float* bp   = (const float*)d_in[10];
    float* out = (float*)d_out;

    quant_kernel<<<5, 1024>>>(Wc1, (const float*)d_in[4], (const float*)d_in[6],
                              (const float*)d_in[8], (const float*)d_in[9]);
    flo_kernel<<<(BB*HWP)/256, 256>>>(flow, bf1, bf2, out);
    conv1_kernel<<<dim3(HWP/WW, BB), 256>>>(corr, bc1);
    dw_kernel<<<dim3(HH/8, CM, BB), 256>>>();
    pw_kernel<<<dim3(HWP/WW, BB), 256>>>(bp, out);
}

// round 4
// speedup vs baseline: 2.3734x; 1.2851x over previous
#include <cuda_runtime.h>
#include <cstdint>

#define BB 16
#define HH 96
#define WW 128
#define HWP (HH*WW)        // 12288
#define CP 196
#define C1 96
#define CF1 64
#define CF2 32
#define CM 128
#define CO 80
#define OUTC 82

// ---- scratch + quantized weights (device globals) -------------------------
__device__ float g_corflo[(size_t)BB*CM*HWP];   // [B,128,H,W]
__device__ float g_dw[(size_t)BB*CM*HWP];       // depthwise result
__device__ float g_Wc1q[C1*CP];                 // quantized, [oc][k]
__device__ float g_Wf1[CF1*2];
__device__ float g_Wf2[CF2*CF1];
__device__ float g_Wd[CM*9];
__device__ float g_Wpq[CO*CM];                  // quantized, [oc][k]

__device__ __forceinline__ float totf32(float x) {   // round-to-nearest tf32
    float r; asm("cvt.rna.tf32.f32 %0, %1;" : "=f"(r) : "f"(x)); return r;
}
__device__ __forceinline__ void mma16n8k8(float* d, const uint32_t* a,
                                          const uint32_t* b) {
    asm volatile(
        "mma.sync.aligned.m16n8k8.row.col.f32.tf32.tf32.f32 "
        "{%0,%1,%2,%3}, {%4,%5,%6,%7}, {%8,%9}, {%0,%1,%2,%3};"
        : "+f"(d[0]), "+f"(d[1]), "+f"(d[2]), "+f"(d[3])
        : "r"(a[0]), "r"(a[1]), "r"(a[2]), "r"(a[3]), "r"(b[0]), "r"(b[1]));
}

// ---------------------------------------------------------------------------
// Per-tensor symmetric int8 fake-quant. One block per tensor.
// ---------------------------------------------------------------------------
__global__ void quant_kernel(const float* __restrict__ Wc1,
                             const float* __restrict__ Wf1,
                             const float* __restrict__ Wf2,
                             const float* __restrict__ Wd,
                             const float* __restrict__ Wp) {
    __shared__ float smax[1024];
    __shared__ float sscale;
    int t = blockIdx.x;
    const float* src; int n;
    if (t == 0)      { src = Wc1; n = C1*CP;   }
    else if (t == 1) { src = Wf1; n = CF1*2;   }
    else if (t == 2) { src = Wf2; n = CF2*CF1; }
    else if (t == 3) { src = Wd;  n = CM*9;    }
    else             { src = Wp;  n = CO*CM;   }

    float m = 0.f;
    for (int i = threadIdx.x; i < n; i += 1024) m = fmaxf(m, fabsf(src[i]));
    smax[threadIdx.x] = m;
    __syncthreads();
    for (int s = 512; s > 0; s >>= 1) {
        if (threadIdx.x < s)
            smax[threadIdx.x] = fmaxf(smax[threadIdx.x], smax[threadIdx.x + s]);
        __syncthreads();
    }
    if (threadIdx.x == 0) sscale = fmaxf(smax[0], 1e-8f) / 127.f;
    __syncthreads();
    float sc = sscale, inv = 1.f / sc;

    for (int i = threadIdx.x; i < n; i += 1024) {
        float q = rintf(src[i] * inv);
        q = fminf(fmaxf(q, -127.f), 127.f) * sc;
        if (t == 0)      g_Wc1q[i] = q;
        else if (t == 1) g_Wf1[i] = q;
        else if (t == 2) g_Wf2[i] = q;
        else if (t == 3) g_Wd[i]  = q;
        else             g_Wpq[i] = q;
    }
}

// ---------------------------------------------------------------------------
// Flow MLP 2->64->32 (relu) -> cor_flo ch [96,128); flow passthrough -> out.
// ---------------------------------------------------------------------------
__global__ void flo_kernel(const float* __restrict__ flow,
                           const float* __restrict__ bf1,
                           const float* __restrict__ bf2,
                           float* __restrict__ out) {
    __shared__ float sW1[CF1*2], sb1[CF1], sW2[CF2*CF1], sb2[CF2];
    int tid = threadIdx.x;
    for (int i = tid; i < CF1*2;   i += 256) sW1[i] = g_Wf1[i];
    for (int i = tid; i < CF1;     i += 256) sb1[i] = bf1[i];
    for (int i = tid; i < CF2*CF1; i += 256) sW2[i] = g_Wf2[i];
    for (int i = tid; i < CF2;     i += 256) sb2[i] = bf2[i];
    __syncthreads();

    int gid = blockIdx.x * 256 + tid;
    int b = gid / HWP, px = gid % HWP;
    float f0 = flow[((size_t)b*2 + 0)*HWP + px];
    float f1 = flow[((size_t)b*2 + 1)*HWP + px];

    float hid[CF1];
#pragma unroll
    for (int h = 0; h < CF1; h++)
        hid[h] = fmaxf(f0*sW1[h*2] + f1*sW1[h*2+1] + sb1[h], 0.f);

#pragma unroll
    for (int o = 0; o < CF2; o++) {
        float a = sb2[o];
#pragma unroll
        for (int h = 0; h < CF1; h++) a += hid[h] * sW2[o*CF1 + h];
        g_corflo[((size_t)(b*CM + C1 + o))*HWP + px] = fmaxf(a, 0.f);
    }
    out[((size_t)(b*OUTC + 80))*HWP + px] = f0;
    out[((size_t)(b*OUTC + 81))*HWP + px] = f1;
}

// ---------------------------------------------------------------------------
// tf32 mma.sync GEMM: D[128 px, NOC oc] = X^T * W^T per 128-px tile.
// X: [b][KTOT][HWP] channel-major. W: [NOC][KTOT]. Y: relu(D+bias),
// channel-major with batch stride OSTR*HWP.
// Block 256 thr = 4 px-warps x 2 oc-warps. Warp: 2 m-tiles x (NOC/16) n-tiles.
// Smem stride 36 floats -> every fragment LDS is bank-conflict-free.
// ---------------------------------------------------------------------------
#define KSTR 36
template<int NOC, int KTOT, int OSTR>
__global__ void __launch_bounds__(256)
gemm_mma(const float* __restrict__ X, const float* __restrict__ W,
         const float* __restrict__ bias, float* __restrict__ Y) {
    constexpr int NCH = (KTOT + 31) / 32;
    constexpr int NT  = NOC / 16;            // n-tiles per warp
    constexpr int STAGE_F = 128*KSTR + NOC*KSTR;
    constexpr int OUT_F   = NOC*128;
    constexpr int SMEMF   = STAGE_F > OUT_F ? STAGE_F : OUT_F;
    __shared__ __align__(16) float smem_f[SMEMF];
    float* As = smem_f;                      // [128][KSTR]
    float* Bs = smem_f + 128*KSTR;           // [NOC][KSTR]

    int tid  = threadIdx.x;
    int wid  = tid >> 5, lane = tid & 31;
    int r    = lane >> 2, c = lane & 3;
    int wpx  = (wid & 3) * 32;               // warp px base
    int woc  = (wid >> 2) * (NOC / 2);       // warp oc base
    int b    = blockIdx.y;
    int px0  = blockIdx.x * 128;

    const float* Xb = X + (size_t)b * KTOT * HWP + px0;

    float acc[2][NT][4];
#pragma unroll
    for (int mt = 0; mt < 2; mt++)
#pragma unroll
        for (int nt = 0; nt < NT; nt++)
#pragma unroll
            for (int i = 0; i < 4; i++) acc[mt][nt][i] = 0.f;

    for (int ch = 0; ch < NCH; ch++) {
        int k0 = ch * 32;
        if (ch) __syncthreads();
        // stage A: [px][k] transpose; 4 coalesced LDG.32 + 1 STS.128 per item
        for (int i = tid; i < 1024; i += 256) {
            int kg = i >> 7, px = i & 127;
            float4 v;
            if (k0 + kg*4 + 3 < KTOT) {
                int kb = k0 + kg*4;
                v.x = totf32(Xb[(size_t)(kb+0)*HWP + px]);
                v.y = totf32(Xb[(size_t)(kb+1)*HWP + px]);
                v.z = totf32(Xb[(size_t)(kb+2)*HWP + px]);
                v.w = totf32(Xb[(size_t)(kb+3)*HWP + px]);
            } else v = make_float4(0.f, 0.f, 0.f, 0.f);
            *(float4*)&As[px*KSTR + kg*4] = v;
        }
        // stage B: [oc][k]; contiguous float4 LDG
        for (int i = tid; i < NOC*8; i += 256) {
            int oc = i >> 3, kg = i & 7;
            float4 v;
            if (k0 + kg*4 + 3 < KTOT) {
                v = *(const float4*)&W[oc*KTOT + k0 + kg*4];
                v.x = totf32(v.x); v.y = totf32(v.y);
                v.z = totf32(v.z); v.w = totf32(v.w);
            } else v = make_float4(0.f, 0.f, 0.f, 0.f);
            *(float4*)&Bs[oc*KSTR + kg*4] = v;
        }
        __syncthreads();

#pragma unroll
        for (int ks = 0; ks < 4; ks++) {
            int kk = ks * 8;
            uint32_t a[2][4], bf[NT][2];
#pragma unroll
            for (int mt = 0; mt < 2; mt++) {
                int row = wpx + mt*16 + r;
                a[mt][0] = __float_as_uint(As[(row  )*KSTR + kk + c    ]);
                a[mt][1] = __float_as_uint(As[(row+8)*KSTR + kk + c    ]);
                a[mt][2] = __float_as_uint(As[(row  )*KSTR + kk + c + 4]);
                a[mt][3] = __float_as_uint(As[(row+8)*KSTR + kk + c + 4]);
            }
#pragma unroll
            for (int nt = 0; nt < NT; nt++) {
                int oc = woc + nt*8 + r;
                bf[nt][0] = __float_as_uint(Bs[oc*KSTR + kk + c    ]);
                bf[nt][1] = __float_as_uint(Bs[oc*KSTR + kk + c + 4]);
            }
#pragma unroll
            for (int mt = 0; mt < 2; mt++)
#pragma unroll
                for (int nt = 0; nt < NT; nt++)
                    mma16n8k8(acc[mt][nt], a[mt], bf[nt]);
        }
    }

    // epilogue: transpose through smem -> coalesced channel-major stores
    __syncthreads();
    float* sOut = smem_f;                    // [NOC][128]
#pragma unroll
    for (int mt = 0; mt < 2; mt++) {
        int row = wpx + mt*16 + r;
#pragma unroll
        for (int nt = 0; nt < NT; nt++) {
            int col = woc + nt*8 + c*2;
            sOut[(col  )*128 + row    ] = acc[mt][nt][0];
            sOut[(col+1)*128 + row    ] = acc[mt][nt][1];
            sOut[(col  )*128 + row + 8] = acc[mt][nt][2];
            sOut[(col+1)*128 + row + 8] = acc[mt][nt][3];
        }
    }
    __syncthreads();

    size_t ob = (size_t)b * OSTR * HWP + px0;
    for (int i = tid; i < NOC*32; i += 256) {
        int oc = i >> 5, p4 = (i & 31) * 4;
        float bi = bias[oc];
        float4 v = *(float4*)&sOut[oc*128 + p4];
        v.x = fmaxf(v.x + bi, 0.f); v.y = fmaxf(v.y + bi, 0.f);
        v.z = fmaxf(v.z + bi, 0.f); v.w = fmaxf(v.w + bi, 0.f);
        *(float4*)&Y[ob + (size_t)oc*HWP + p4] = v;
    }
}

// ---------------------------------------------------------------------------
// Depthwise 3x3 (pad=1): elementwise, float4 in/out.
// ---------------------------------------------------------------------------
__global__ void dw_kernel() {
    int c   = blockIdx.y, b = blockIdx.z;
    int sub = threadIdx.x >> 5;
    int xq  = (threadIdx.x & 31) * 4;
    int y   = blockIdx.x * 8 + sub;

    const float* base = g_corflo + ((size_t)(b*CM + c))*HWP + y*WW + xq;
    float w[9];
#pragma unroll
    for (int i = 0; i < 9; i++) w[i] = g_Wd[c*9 + i];

    float4 a = make_float4(0.f, 0.f, 0.f, 0.f);
#pragma unroll
    for (int r = 0; r < 3; r++) {
        int gy = y - 1 + r;
        if ((unsigned)gy >= HH) continue;
        const float* rp = base + (r-1)*WW;
        float4 f = *(const float4*)rp;
        float xl = (xq > 0)      ? rp[-1] : 0.f;
        float xr = (xq < WW - 4) ? rp[4]  : 0.f;
        float w0 = w[r*3], w1 = w[r*3+1], w2 = w[r*3+2];
        a.x += w0*xl  + w1*f.x + w2*f.y;
        a.y += w0*f.x + w1*f.y + w2*f.z;
        a.z += w0*f.y + w1*f.z + w2*f.w;
        a.w += w0*f.z + w1*f.w + w2*xr;
    }
    *(float4*)(g_dw + ((size_t)(b*CM + c))*HWP + y*WW + xq) = a;
}

// ---------------------------------------------------------------------------
extern "C" void kernel_launch(void* const* d_in, const int* in_sizes, int n_in,
                              void* d_out, int out_size) {
    const float* flow = (const float*)d_in[0];
    const float* corr = (const float*)d_in[1];
    const float* Wc1  = (const float*)d_in[2];
    const float* bc1  = (const float*)d_in[3];
    const float* bf1  = (const float*)d_in[5];
    const float* bf2  = (const float*)d_in[7];
    const float* bp   = (const float*)d_in[10];
    float* out = (float*)d_out;

    float* wc1q; cudaGetSymbolAddress((void**)&wc1q, g_Wc1q);
    float* wpq;  cudaGetSymbolAddress((void**)&wpq,  g_Wpq);
    float* dwp;  cudaGetSymbolAddress((void**)&dwp,  g_dw);
    float* cfp;  cudaGetSymbolAddress((void**)&cfp,  g_corflo);

    quant_kernel<<<5, 1024>>>(Wc1, (const float*)d_in[4], (const float*)d_in[6],
                              (const float*)d_in[8], (const float*)d_in[9]);
    flo_kernel<<<(BB*HWP)/256, 256>>>(flow, bf1, bf2, out);
    gemm_mma<C1, CP, CM><<<dim3(HWP/128, BB), 256>>>(corr, wc1q, bc1, cfp);
    dw_kernel<<<dim3(HH/8, CM, BB), 256>>>();
    gemm_mma<CO, CM, OUTC><<<dim3(HWP/128, BB), 256>>>(dwp, wpq, bp, out);
}

// round 5
// speedup vs baseline: 2.7665x; 1.1656x over previous
#include <cuda_runtime.h>
#include <cstdint>

#define BB 16
#define HH 96
#define WW 128
#define HWP (HH*WW)        // 12288
#define CP 196
#define C1 96
#define CF1 64
#define CF2 32
#define CM 128
#define CO 80
#define OUTC 82
#define KSTR 36

// ---- scratch + quantized weights (device globals) -------------------------
__device__ float g_corflo[(size_t)BB*CM*HWP];   // [B,128,H,W]
__device__ float g_Wc1q[C1*CP];                 // quantized, [oc][k]
__device__ float g_Wf1[CF1*2];
__device__ float g_Wf2[CF2*CF1];
__device__ float g_Wd[CM*9];
__device__ float g_Wpq[CO*CM];                  // quantized, [oc][k]

__device__ __forceinline__ float totf32(float x) {   // round-to-nearest tf32
    float r; asm("cvt.rna.tf32.f32 %0, %1;" : "=f"(r) : "f"(x)); return r;
}
__device__ __forceinline__ void mma16n8k8(float* d, const uint32_t* a,
                                          const uint32_t* b) {
    asm volatile(
        "mma.sync.aligned.m16n8k8.row.col.f32.tf32.tf32.f32 "
        "{%0,%1,%2,%3}, {%4,%5,%6,%7}, {%8,%9}, {%0,%1,%2,%3};"
        : "+f"(d[0]), "+f"(d[1]), "+f"(d[2]), "+f"(d[3])
        : "r"(a[0]), "r"(a[1]), "r"(a[2]), "r"(a[3]), "r"(b[0]), "r"(b[1]));
}

// ---------------------------------------------------------------------------
// Per-tensor symmetric int8 fake-quant. One block per tensor.
// ---------------------------------------------------------------------------
__global__ void quant_kernel(const float* __restrict__ Wc1,
                             const float* __restrict__ Wf1,
                             const float* __restrict__ Wf2,
                             const float* __restrict__ Wd,
                             const float* __restrict__ Wp) {
    __shared__ float smax[1024];
    __shared__ float sscale;
    int t = blockIdx.x;
    const float* src; int n;
    if (t == 0)      { src = Wc1; n = C1*CP;   }
    else if (t == 1) { src = Wf1; n = CF1*2;   }
    else if (t == 2) { src = Wf2; n = CF2*CF1; }
    else if (t == 3) { src = Wd;  n = CM*9;    }
    else             { src = Wp;  n = CO*CM;   }

    float m = 0.f;
    for (int i = threadIdx.x; i < n; i += 1024) m = fmaxf(m, fabsf(src[i]));
    smax[threadIdx.x] = m;
    __syncthreads();
    for (int s = 512; s > 0; s >>= 1) {
        if (threadIdx.x < s)
            smax[threadIdx.x] = fmaxf(smax[threadIdx.x], smax[threadIdx.x + s]);
        __syncthreads();
    }
    if (threadIdx.x == 0) sscale = fmaxf(smax[0], 1e-8f) / 127.f;
    __syncthreads();
    float sc = sscale, inv = 1.f / sc;

    for (int i = threadIdx.x; i < n; i += 1024) {
        float q = rintf(src[i] * inv);
        q = fminf(fmaxf(q, -127.f), 127.f) * sc;
        if (t == 0)      g_Wc1q[i] = q;
        else if (t == 1) g_Wf1[i] = q;
        else if (t == 2) g_Wf2[i] = q;
        else if (t == 3) g_Wd[i]  = q;
        else             g_Wpq[i] = q;
    }
}

// ---------------------------------------------------------------------------
// Merged kernel: blocks x<96 run conv1 (tf32 GEMM, register-prefetch double
// buffer); blocks x>=96 run the flow MLP. Both write g_corflo; flo also
// writes the flow passthrough to out ch 80,81.
// ---------------------------------------------------------------------------
__global__ void __launch_bounds__(256)
convflo_kernel(const float* __restrict__ corr, const float* __restrict__ bc1,
               const float* __restrict__ flow, const float* __restrict__ bf1,
               const float* __restrict__ bf2, float* __restrict__ out) {
    __shared__ __align__(16) float smem_f[C1*128];   // 12288 floats (49KB)
    int tid = threadIdx.x;
    int b   = blockIdx.y;

    if (blockIdx.x >= HWP/128) {
        // ---------------- flo part ----------------
        float* sW1 = smem_f;            // 128
        float* sb1 = sW1 + CF1*2;       // 64
        float* sW2 = sb1 + CF1;         // 2048
        float* sb2 = sW2 + CF2*CF1;     // 32
        for (int i = tid; i < CF1*2;   i += 256) sW1[i] = g_Wf1[i];
        for (int i = tid; i < CF1;     i += 256) sb1[i] = bf1[i];
        for (int i = tid; i < CF2*CF1; i += 256) sW2[i] = g_Wf2[i];
        for (int i = tid; i < CF2;     i += 256) sb2[i] = bf2[i];
        __syncthreads();

        int px = (blockIdx.x - HWP/128) * 256 + tid;   // 0..12287
        float f0 = flow[((size_t)b*2 + 0)*HWP + px];
        float f1 = flow[((size_t)b*2 + 1)*HWP + px];

        float hid[CF1];
#pragma unroll
        for (int h = 0; h < CF1; h++)
            hid[h] = fmaxf(f0*sW1[h*2] + f1*sW1[h*2+1] + sb1[h], 0.f);
#pragma unroll
        for (int o = 0; o < CF2; o++) {
            float a = sb2[o];
#pragma unroll
            for (int h = 0; h < CF1; h++) a += hid[h] * sW2[o*CF1 + h];
            g_corflo[((size_t)(b*CM + C1 + o))*HWP + px] = fmaxf(a, 0.f);
        }
        out[((size_t)(b*OUTC + 80))*HWP + px] = f0;
        out[((size_t)(b*OUTC + 81))*HWP + px] = f1;
        return;
    }

    // ---------------- conv1 part: 128px x 96oc tf32 GEMM ----------------
    constexpr int NCH = (CP + 31) / 32;     // 7
    constexpr int NT  = C1 / 16;            // 6
    float* As = smem_f;                     // [128][KSTR]
    float* Bs = smem_f + 128*KSTR;          // [96][KSTR]

    int wid  = tid >> 5, lane = tid & 31;
    int r    = lane >> 2, c = lane & 3;
    int wpx  = (wid & 3) * 32;
    int woc  = (wid >> 2) * (C1 / 2);
    int px0  = blockIdx.x * 128;
    const float* Xb = corr + (size_t)b * CP * HWP + px0;

    float acc[2][NT][4];
#pragma unroll
    for (int mt = 0; mt < 2; mt++)
#pragma unroll
        for (int nt = 0; nt < NT; nt++)
#pragma unroll
            for (int i = 0; i < 4; i++) acc[mt][nt][i] = 0.f;

    float  pa[16];
    float4 pb[3];
    // prefetch chunk 0
#pragma unroll
    for (int v = 0; v < 4; v++) {
        int i = tid + 256*v;
        int kg = i >> 7, px = i & 127, kb = kg*4;
        if (kb + 3 < CP) {
#pragma unroll
            for (int j = 0; j < 4; j++) pa[v*4+j] = Xb[(size_t)(kb+j)*HWP + px];
        } else { pa[v*4]=pa[v*4+1]=pa[v*4+2]=pa[v*4+3]=0.f; }
    }
#pragma unroll
    for (int v = 0; v < 3; v++) {
        int i = tid + 256*v;
        int oc = i >> 3, kg = i & 7, kb = kg*4;
        pb[v] = (kb + 3 < CP) ? *(const float4*)&g_Wc1q[oc*CP + kb]
                              : make_float4(0.f,0.f,0.f,0.f);
    }

    for (int ch = 0; ch < NCH; ch++) {
        // store prefetched chunk to smem (tf32 rounding at store)
#pragma unroll
        for (int v = 0; v < 4; v++) {
            int i = tid + 256*v;
            int kg = i >> 7, px = i & 127;
            float4 s = make_float4(totf32(pa[v*4]), totf32(pa[v*4+1]),
                                   totf32(pa[v*4+2]), totf32(pa[v*4+3]));
            *(float4*)&As[px*KSTR + kg*4] = s;
        }
#pragma unroll
        for (int v = 0; v < 3; v++) {
            int i = tid + 256*v;
            int oc = i >> 3, kg = i & 7;
            float4 s = make_float4(totf32(pb[v].x), totf32(pb[v].y),
                                   totf32(pb[v].z), totf32(pb[v].w));
            *(float4*)&Bs[oc*KSTR + kg*4] = s;
        }
        __syncthreads();

        // prefetch next chunk (LDG latency overlaps mma below)
        if (ch + 1 < NCH) {
            int k0n = (ch + 1) * 32;
#pragma unroll
            for (int v = 0; v < 4; v++) {
                int i = tid + 256*v;
                int kg = i >> 7, px = i & 127, kb = k0n + kg*4;
                if (kb + 3 < CP) {
#pragma unroll
                    for (int j = 0; j < 4; j++)
                        pa[v*4+j] = Xb[(size_t)(kb+j)*HWP + px];
                } else { pa[v*4]=pa[v*4+1]=pa[v*4+2]=pa[v*4+3]=0.f; }
            }
#pragma unroll
            for (int v = 0; v < 3; v++) {
                int i = tid + 256*v;
                int oc = i >> 3, kg = i & 7, kb = k0n + kg*4;
                pb[v] = (kb + 3 < CP) ? *(const float4*)&g_Wc1q[oc*CP + kb]
                                      : make_float4(0.f,0.f,0.f,0.f);
            }
        }

#pragma unroll
        for (int ks = 0; ks < 4; ks++) {
            int kk = ks * 8;
            uint32_t a[2][4], bf[NT][2];
#pragma unroll
            for (int mt = 0; mt < 2; mt++) {
                int row = wpx + mt*16 + r;
                a[mt][0] = __float_as_uint(As[(row  )*KSTR + kk + c    ]);
                a[mt][1] = __float_as_uint(As[(row+8)*KSTR + kk + c    ]);
                a[mt][2] = __float_as_uint(As[(row  )*KSTR + kk + c + 4]);
                a[mt][3] = __float_as_uint(As[(row+8)*KSTR + kk + c + 4]);
            }
#pragma unroll
            for (int nt = 0; nt < NT; nt++) {
                int oc = woc + nt*8 + r;
                bf[nt][0] = __float_as_uint(Bs[oc*KSTR + kk + c    ]);
                bf[nt][1] = __float_as_uint(Bs[oc*KSTR + kk + c + 4]);
            }
#pragma unroll
            for (int mt = 0; mt < 2; mt++)
#pragma unroll
                for (int nt = 0; nt < NT; nt++)
                    mma16n8k8(acc[mt][nt], a[mt], bf[nt]);
        }
        __syncthreads();
    }

    // epilogue: transpose through smem -> coalesced channel-major stores
    float* sOut = smem_f;                    // [96][128]
#pragma unroll
    for (int mt = 0; mt < 2; mt++) {
        int row = wpx + mt*16 + r;
#pragma unroll
        for (int nt = 0; nt < NT; nt++) {
            int col = woc + nt*8 + c*2;
            sOut[(col  )*128 + row    ] = acc[mt][nt][0];
            sOut[(col+1)*128 + row    ] = acc[mt][nt][1];
            sOut[(col  )*128 + row + 8] = acc[mt][nt][2];
            sOut[(col+1)*128 + row + 8] = acc[mt][nt][3];
        }
    }
    __syncthreads();

    size_t ob = (size_t)b * CM * HWP + px0;
    for (int i = tid; i < C1*32; i += 256) {
        int oc = i >> 5, p4 = (i & 31) * 4;
        float bi = bc1[oc];
        float4 v = *(float4*)&sOut[oc*128 + p4];
        v.x = fmaxf(v.x + bi, 0.f); v.y = fmaxf(v.y + bi, 0.f);
        v.z = fmaxf(v.z + bi, 0.f); v.w = fmaxf(v.w + bi, 0.f);
        *(float4*)&g_corflo[ob + (size_t)oc*HWP + p4] = v;
    }
}

// ---------------------------------------------------------------------------
// Fused depthwise-3x3 + pointwise 128->80 tf32 GEMM + bias + relu.
// Block = one (b, row y): 128 px. K chunks of 32 channels:
//   stage 3 halo rows into smem -> compute dw into tf32 A-tile -> mma.
// Dynamic smem ~84KB.
// ---------------------------------------------------------------------------
#define RST 136   // raw row stride (floats): data at [4+x], halo at [3],[132]
#define RAWF (3*32*RST)
__global__ void __launch_bounds__(256)
pwdw_kernel(const float* __restrict__ bp, float* __restrict__ out) {
    extern __shared__ __align__(16) float dsm[];
    float* raw = dsm;                    // 13056
    float* As  = dsm + RAWF;             // [128][KSTR] 4608
    float* Bs  = As + 128*KSTR;          // [80][KSTR]  2880
    float* wds = Bs + CO*KSTR;           // [32][12]    384
    float* sb  = wds + 32*12;            // 80

    constexpr int NT = CO / 16;          // 5
    int tid = threadIdx.x;
    int wid = tid >> 5, lane = tid & 31;
    int r   = lane >> 2, c = lane & 3;
    int wpx = (wid & 3) * 32;
    int woc = (wid >> 2) * (CO / 2);
    int y   = blockIdx.x;
    int b   = blockIdx.y;

    for (int i = tid; i < CO; i += 256) sb[i] = bp[i];

    float acc[2][NT][4];
#pragma unroll
    for (int mt = 0; mt < 2; mt++)
#pragma unroll
        for (int nt = 0; nt < NT; nt++)
#pragma unroll
            for (int i = 0; i < 4; i++) acc[mt][nt][i] = 0.f;

    for (int ck = 0; ck < 4; ck++) {
        int k0 = ck * 32;
        if (ck) __syncthreads();
        // stage raw rows y-1..y+1 for 32 channels (float4, zero OOB rows)
        for (int i = tid; i < 3*32*32; i += 256) {
            int rr = i >> 10;                  // /1024
            int rem = i & 1023;
            int cc = rem >> 5, x4 = (rem & 31) * 4;
            int gy = y - 1 + rr;
            float4 v = make_float4(0.f, 0.f, 0.f, 0.f);
            if ((unsigned)gy < HH)
                v = *(const float4*)&g_corflo[((size_t)(b*CM + k0 + cc))*HWP
                                              + gy*WW + x4];
            *(float4*)&raw[(rr*32 + cc)*RST + 4 + x4] = v;
        }
        if (tid < 96) {                        // zero x-halos
            raw[tid*RST + 3]   = 0.f;
            raw[tid*RST + 132] = 0.f;
        }
        for (int i = tid; i < 32*9; i += 256)
            wds[(i/9)*12 + (i%9)] = g_Wd[(k0 + i/9)*9 + (i%9)];
        for (int i = tid; i < CO*8; i += 256) {
            int oc = i >> 3, kg = i & 7;
            float4 v = *(const float4*)&g_Wpq[oc*CM + k0 + kg*4];
            v.x = totf32(v.x); v.y = totf32(v.y);
            v.z = totf32(v.z); v.w = totf32(v.w);
            *(float4*)&Bs[oc*KSTR + kg*4] = v;
        }
        __syncthreads();

        // depthwise into A-tile: thread -> 4 channels x 1 px, STS.128
#pragma unroll
        for (int v = 0; v < 4; v++) {
            int i = tid + 256*v;
            int kq = i >> 7, px = i & 127;
            float o4[4];
#pragma unroll
            for (int j = 0; j < 4; j++) {
                int cc = kq*4 + j;
                float a = 0.f;
#pragma unroll
                for (int rr = 0; rr < 3; rr++) {
                    const float* rp = &raw[(rr*32 + cc)*RST + 4 + px];
                    const float* wp = &wds[cc*12 + rr*3];
                    a += rp[-1]*wp[0] + rp[0]*wp[1] + rp[1]*wp[2];
                }
                o4[j] = totf32(a);
            }
            *(float4*)&As[px*KSTR + kq*4] = make_float4(o4[0],o4[1],o4[2],o4[3]);
        }
        __syncthreads();

#pragma unroll
        for (int ks = 0; ks < 4; ks++) {
            int kk = ks * 8;
            uint32_t a[2][4], bf[NT][2];
#pragma unroll
            for (int mt = 0; mt < 2; mt++) {
                int row = wpx + mt*16 + r;
                a[mt][0] = __float_as_uint(As[(row  )*KSTR + kk + c    ]);
                a[mt][1] = __float_as_uint(As[(row+8)*KSTR + kk + c    ]);
                a[mt][2] = __float_as_uint(As[(row  )*KSTR + kk + c + 4]);
                a[mt][3] = __float_as_uint(As[(row+8)*KSTR + kk + c + 4]);
            }
#pragma unroll
            for (int nt = 0; nt < NT; nt++) {
                int oc = woc + nt*8 + r;
                bf[nt][0] = __float_as_uint(Bs[oc*KSTR + kk + c    ]);
                bf[nt][1] = __float_as_uint(Bs[oc*KSTR + kk + c + 4]);
            }
#pragma unroll
            for (int mt = 0; mt < 2; mt++)
#pragma unroll
                for (int nt = 0; nt < NT; nt++)
                    mma16n8k8(acc[mt][nt], a[mt], bf[nt]);
        }
    }

    // epilogue: transpose via smem (reuse raw region) -> coalesced stores
    __syncthreads();
    float* sOut = dsm;                   // [80][128] = 10240 <= RAWF
#pragma unroll
    for (int mt = 0; mt < 2; mt++) {
        int row = wpx + mt*16 + r;
#pragma unroll
        for (int nt = 0; nt < NT; nt++) {
            int col = woc + nt*8 + c*2;
            sOut[(col  )*128 + row    ] = acc[mt][nt][0];
            sOut[(col+1)*128 + row    ] = acc[mt][nt][1];
            sOut[(col  )*128 + row + 8] = acc[mt][nt][2];
            sOut[(col+1)*128 + row + 8] = acc[mt][nt][3];
        }
    }
    __syncthreads();

    size_t ob = (size_t)b * OUTC * HWP + (size_t)y * WW;
    for (int i = tid; i < CO*32; i += 256) {
        int oc = i >> 5, p4 = (i & 31) * 4;
        float bi = sb[oc];
        float4 v = *(float4*)&sOut[oc*128 + p4];
        v.x = fmaxf(v.x + bi, 0.f); v.y = fmaxf(v.y + bi, 0.f);
        v.z = fmaxf(v.z + bi, 0.f); v.w = fmaxf(v.w + bi, 0.f);
        *(float4*)&out[ob + (size_t)oc*HWP + p4] = v;
    }
}

// ---------------------------------------------------------------------------
extern "C" void kernel_launch(void* const* d_in, const int* in_sizes, int n_in,
                              void* d_out, int out_size) {
    const float* flow = (const float*)d_in[0];
    const float* corr = (const float*)d_in[1];
    const float* Wc1  = (const float*)d_in[2];
    const float* bc1  = (const float*)d_in[3];
    const float* bf1  = (const float*)d_in[5];
    const float* bf2  = (const float*)d_in[7];
    const float* bp   = (const float*)d_in[10];
    float* out = (float*)d_out;

    const int PWDW_SMEM = (RAWF + 128*KSTR + CO*KSTR + 32*12 + CO) * 4;
    cudaFuncSetAttribute(pwdw_kernel,
                         cudaFuncAttributeMaxDynamicSharedMemorySize, PWDW_SMEM);

    quant_kernel<<<5, 1024>>>(Wc1, (const float*)d_in[4], (const float*)d_in[6],
                              (const float*)d_in[8], (const float*)d_in[9]);
    convflo_kernel<<<dim3(HWP/128 + HWP/256, BB), 256>>>(corr, bc1, flow,
                                                         bf1, bf2, out);
    pwdw_kernel<<<dim3(HH, BB), 256, PWDW_SMEM>>>(bp, out);
}

// round 6
// speedup vs baseline: 3.0796x; 1.1132x over previous
#include <cuda_runtime.h>
#include <cstdint>

#define BB 16
#define HH 96
#define WW 128
#define HWP (HH*WW)        // 12288
#define CP 196
#define C1 96
#define CF1 64
#define CF2 32
#define CM 128
#define CO 80
#define OUTC 82
#define KSTR 36

// ---- scratch + quantized weights (device globals) -------------------------
__device__ float g_corflo[(size_t)BB*CM*HWP];   // [B,128,H,W]
__device__ float g_Wc1q[C1*CP];                 // quantized, [oc][k]
__device__ float g_Wf1[CF1*2];
__device__ float g_Wf2[CF2*CF1];
__device__ float g_Wd[CM*9];
__device__ float g_Wpq[CO*CM];                  // quantized, [oc][k]

__device__ __forceinline__ float totf32(float x) {   // round-to-nearest tf32
    float r; asm("cvt.rna.tf32.f32 %0, %1;" : "=f"(r) : "f"(x)); return r;
}
__device__ __forceinline__ void mma16n8k8(float* d, const uint32_t* a,
                                          const uint32_t* b) {
    asm volatile(
        "mma.sync.aligned.m16n8k8.row.col.f32.tf32.tf32.f32 "
        "{%0,%1,%2,%3}, {%4,%5,%6,%7}, {%8,%9}, {%0,%1,%2,%3};"
        : "+f"(d[0]), "+f"(d[1]), "+f"(d[2]), "+f"(d[3])
        : "r"(a[0]), "r"(a[1]), "r"(a[2]), "r"(a[3]), "r"(b[0]), "r"(b[1]));
}
__device__ __forceinline__ uint32_t smem_u32(const void* p) {
    uint32_t a;
    asm("{ .reg .u64 t; cvta.to.shared.u64 t, %1; cvt.u32.u64 %0, t; }"
        : "=r"(a) : "l"(p));
    return a;
}
__device__ __forceinline__ void cp16(uint32_t dst, const void* src, int sz) {
    asm volatile("cp.async.ca.shared.global [%0], [%1], 16, %2;"
                 :: "r"(dst), "l"(src), "r"(sz) : "memory");
}
#define CP_COMMIT() asm volatile("cp.async.commit_group;" ::: "memory")
template<int N> __device__ __forceinline__ void cp_wait() {
    asm volatile("cp.async.wait_group %0;" :: "n"(N) : "memory");
}

// ---------------------------------------------------------------------------
// Per-tensor symmetric int8 fake-quant. One block per tensor.
// ---------------------------------------------------------------------------
__global__ void quant_kernel(const float* __restrict__ Wc1,
                             const float* __restrict__ Wf1,
                             const float* __restrict__ Wf2,
                             const float* __restrict__ Wd,
                             const float* __restrict__ Wp) {
    __shared__ float smax[1024];
    __shared__ float sscale;
    int t = blockIdx.x;
    const float* src; int n;
    if (t == 0)      { src = Wc1; n = C1*CP;   }
    else if (t == 1) { src = Wf1; n = CF1*2;   }
    else if (t == 2) { src = Wf2; n = CF2*CF1; }
    else if (t == 3) { src = Wd;  n = CM*9;    }
    else             { src = Wp;  n = CO*CM;   }

    float m = 0.f;
    for (int i = threadIdx.x; i < n; i += 1024) m = fmaxf(m, fabsf(src[i]));
    smax[threadIdx.x] = m;
    __syncthreads();
    for (int s = 512; s > 0; s >>= 1) {
        if (threadIdx.x < s)
            smax[threadIdx.x] = fmaxf(smax[threadIdx.x], smax[threadIdx.x + s]);
        __syncthreads();
    }
    if (threadIdx.x == 0) sscale = fmaxf(smax[0], 1e-8f) / 127.f;
    __syncthreads();
    float sc = sscale, inv = 1.f / sc;

    for (int i = threadIdx.x; i < n; i += 1024) {
        float q = rintf(src[i] * inv);
        q = fminf(fmaxf(q, -127.f), 127.f) * sc;
        if (t == 0)      g_Wc1q[i] = q;
        else if (t == 1) g_Wf1[i] = q;
        else if (t == 2) g_Wf2[i] = q;
        else if (t == 3) g_Wd[i]  = q;
        else             g_Wpq[i] = q;
    }
}

// ---------------------------------------------------------------------------
// Merged kernel: blocks x<96 run conv1 (tf32 GEMM, register-prefetch double
// buffer); blocks x>=96 run the flow MLP.
// ---------------------------------------------------------------------------
__global__ void __launch_bounds__(256)
convflo_kernel(const float* __restrict__ corr, const float* __restrict__ bc1,
               const float* __restrict__ flow, const float* __restrict__ bf1,
               const float* __restrict__ bf2, float* __restrict__ out) {
    __shared__ __align__(16) float smem_f[C1*128];
    int tid = threadIdx.x;
    int b   = blockIdx.y;

    if (blockIdx.x >= HWP/128) {
        float* sW1 = smem_f;
        float* sb1 = sW1 + CF1*2;
        float* sW2 = sb1 + CF1;
        float* sb2 = sW2 + CF2*CF1;
        for (int i = tid; i < CF1*2;   i += 256) sW1[i] = g_Wf1[i];
        for (int i = tid; i < CF1;     i += 256) sb1[i] = bf1[i];
        for (int i = tid; i < CF2*CF1; i += 256) sW2[i] = g_Wf2[i];
        for (int i = tid; i < CF2;     i += 256) sb2[i] = bf2[i];
        __syncthreads();

        int px = (blockIdx.x - HWP/128) * 256 + tid;
        float f0 = flow[((size_t)b*2 + 0)*HWP + px];
        float f1 = flow[((size_t)b*2 + 1)*HWP + px];

        float hid[CF1];
#pragma unroll
        for (int h = 0; h < CF1; h++)
            hid[h] = fmaxf(f0*sW1[h*2] + f1*sW1[h*2+1] + sb1[h], 0.f);
#pragma unroll
        for (int o = 0; o < CF2; o++) {
            float a = sb2[o];
#pragma unroll
            for (int h = 0; h < CF1; h++) a += hid[h] * sW2[o*CF1 + h];
            g_corflo[((size_t)(b*CM + C1 + o))*HWP + px] = fmaxf(a, 0.f);
        }
        out[((size_t)(b*OUTC + 80))*HWP + px] = f0;
        out[((size_t)(b*OUTC + 81))*HWP + px] = f1;
        return;
    }

    constexpr int NCH = (CP + 31) / 32;     // 7
    constexpr int NT  = C1 / 16;            // 6
    float* As = smem_f;                     // [128][KSTR]
    float* Bs = smem_f + 128*KSTR;          // [96][KSTR]

    int wid  = tid >> 5, lane = tid & 31;
    int r    = lane >> 2, c = lane & 3;
    int wpx  = (wid & 3) * 32;
    int woc  = (wid >> 2) * (C1 / 2);
    int px0  = blockIdx.x * 128;
    const float* Xb = corr + (size_t)b * CP * HWP + px0;

    float acc[2][NT][4];
#pragma unroll
    for (int mt = 0; mt < 2; mt++)
#pragma unroll
        for (int nt = 0; nt < NT; nt++)
#pragma unroll
            for (int i = 0; i < 4; i++) acc[mt][nt][i] = 0.f;

    float  pa[16];
    float4 pb[3];
#pragma unroll
    for (int v = 0; v < 4; v++) {
        int i = tid + 256*v;
        int kg = i >> 7, px = i & 127, kb = kg*4;
        if (kb + 3 < CP) {
#pragma unroll
            for (int j = 0; j < 4; j++) pa[v*4+j] = Xb[(size_t)(kb+j)*HWP + px];
        } else { pa[v*4]=pa[v*4+1]=pa[v*4+2]=pa[v*4+3]=0.f; }
    }
#pragma unroll
    for (int v = 0; v < 3; v++) {
        int i = tid + 256*v;
        int oc = i >> 3, kg = i & 7, kb = kg*4;
        pb[v] = (kb + 3 < CP) ? *(const float4*)&g_Wc1q[oc*CP + kb]
                              : make_float4(0.f,0.f,0.f,0.f);
    }

    for (int ch = 0; ch < NCH; ch++) {
#pragma unroll
        for (int v = 0; v < 4; v++) {
            int i = tid + 256*v;
            int kg = i >> 7, px = i & 127;
            float4 s = make_float4(totf32(pa[v*4]), totf32(pa[v*4+1]),
                                   totf32(pa[v*4+2]), totf32(pa[v*4+3]));
            *(float4*)&As[px*KSTR + kg*4] = s;
        }
#pragma unroll
        for (int v = 0; v < 3; v++) {
            int i = tid + 256*v;
            int oc = i >> 3, kg = i & 7;
            float4 s = make_float4(totf32(pb[v].x), totf32(pb[v].y),
                                   totf32(pb[v].z), totf32(pb[v].w));
            *(float4*)&Bs[oc*KSTR + kg*4] = s;
        }
        __syncthreads();

        if (ch + 1 < NCH) {
            int k0n = (ch + 1) * 32;
#pragma unroll
            for (int v = 0; v < 4; v++) {
                int i = tid + 256*v;
                int kg = i >> 7, px = i & 127, kb = k0n + kg*4;
                if (kb + 3 < CP) {
#pragma unroll
                    for (int j = 0; j < 4; j++)
                        pa[v*4+j] = Xb[(size_t)(kb+j)*HWP + px];
                } else { pa[v*4]=pa[v*4+1]=pa[v*4+2]=pa[v*4+3]=0.f; }
            }
#pragma unroll
            for (int v = 0; v < 3; v++) {
                int i = tid + 256*v;
                int oc = i >> 3, kg = i & 7, kb = k0n + kg*4;
                pb[v] = (kb + 3 < CP) ? *(const float4*)&g_Wc1q[oc*CP + kb]
                                      : make_float4(0.f,0.f,0.f,0.f);
            }
        }

#pragma unroll
        for (int ks = 0; ks < 4; ks++) {
            int kk = ks * 8;
            uint32_t a[2][4], bf[NT][2];
#pragma unroll
            for (int mt = 0; mt < 2; mt++) {
                int row = wpx + mt*16 + r;
                a[mt][0] = __float_as_uint(As[(row  )*KSTR + kk + c    ]);
                a[mt][1] = __float_as_uint(As[(row+8)*KSTR + kk + c    ]);
                a[mt][2] = __float_as_uint(As[(row  )*KSTR + kk + c + 4]);
                a[mt][3] = __float_as_uint(As[(row+8)*KSTR + kk + c + 4]);
            }
#pragma unroll
            for (int nt = 0; nt < NT; nt++) {
                int oc = woc + nt*8 + r;
                bf[nt][0] = __float_as_uint(Bs[oc*KSTR + kk + c    ]);
                bf[nt][1] = __float_as_uint(Bs[oc*KSTR + kk + c + 4]);
            }
#pragma unroll
            for (int mt = 0; mt < 2; mt++)
#pragma unroll
                for (int nt = 0; nt < NT; nt++)
                    mma16n8k8(acc[mt][nt], a[mt], bf[nt]);
        }
        __syncthreads();
    }

    float* sOut = smem_f;                    // [96][128]
#pragma unroll
    for (int mt = 0; mt < 2; mt++) {
        int row = wpx + mt*16 + r;
#pragma unroll
        for (int nt = 0; nt < NT; nt++) {
            int col = woc + nt*8 + c*2;
            sOut[(col  )*128 + row    ] = acc[mt][nt][0];
            sOut[(col+1)*128 + row    ] = acc[mt][nt][1];
            sOut[(col  )*128 + row + 8] = acc[mt][nt][2];
            sOut[(col+1)*128 + row + 8] = acc[mt][nt][3];
        }
    }
    __syncthreads();

    size_t ob = (size_t)b * CM * HWP + px0;
    for (int i = tid; i < C1*32; i += 256) {
        int oc = i >> 5, p4 = (i & 31) * 4;
        float bi = bc1[oc];
        float4 v = *(float4*)&sOut[oc*128 + p4];
        v.x = fmaxf(v.x + bi, 0.f); v.y = fmaxf(v.y + bi, 0.f);
        v.z = fmaxf(v.z + bi, 0.f); v.w = fmaxf(v.w + bi, 0.f);
        *(float4*)&g_corflo[ob + (size_t)oc*HWP + p4] = v;
    }
}

// ---------------------------------------------------------------------------
// Fused depthwise-3x3 + pointwise 128->80 tf32 GEMM, 2 rows per block.
// cp.async double-buffered halo staging; As in [k][px] (PSTR=264) so dw
// STS.128 is conflict-free and mma A-frag LDS hits 32 distinct banks.
// ---------------------------------------------------------------------------
#define RST  136                 // raw row stride (halo at [3],[132], data 4+x)
#define RAWC (4*32*RST)          // 4 rows x 32 ch per chunk = 17408 floats
#define PSTR 264                 // As pixel stride (256 + 8)
__global__ void __launch_bounds__(256)
pwdw_kernel(const float* __restrict__ bp, float* __restrict__ out) {
    extern __shared__ __align__(16) float dsm[];
    float* raw = dsm;                     // [2][RAWC]
    float* As  = dsm + 2*RAWC;            // [32][PSTR]
    float* Bs  = As  + 32*PSTR;           // [2][80*KSTR]
    float* wds = Bs  + 2*CO*KSTR;         // [2][32*12]
    float* sb  = wds + 2*32*12;           // [80]

    constexpr int NT = CO / 16;           // 5
    int tid = threadIdx.x;
    int wid = tid >> 5, lane = tid & 31;
    int r   = lane >> 2, c = lane & 3;
    int wpx = (wid & 3) * 64;             // 64 px (4 m-tiles) per px-warp
    int woc = (wid >> 2) * (CO / 2);
    int y0  = blockIdx.x * 2;
    int b   = blockIdx.y;

    // zero x-halo slots of both raw buffers (written once, always zero)
    for (int i = tid; i < 2*128; i += 256) {
        int o = (i >> 7) * RAWC + (i & 127) * RST;
        raw[o + 3] = 0.f; raw[o + 132] = 0.f;
    }
    for (int i = tid; i < CO; i += 256) sb[i] = bp[i];

    uint32_t rawb = smem_u32(raw);
    const float* cfb = g_corflo + (size_t)b * CM * HWP;

    // stage raw chunk ck into buffer buf via cp.async (zero-fill OOB rows)
    auto stage_raw = [&](int ck, int buf) {
        int k0 = ck * 32;
        uint32_t db = rawb + (uint32_t)buf * RAWC * 4;
#pragma unroll
        for (int v = 0; v < 16; v++) {
            int i = tid + 256*v;
            int rr = i >> 10, rem = i & 1023;
            int cc = rem >> 5, x4 = (rem & 31) * 4;
            int gy = y0 - 1 + rr;
            const float* src = cfb + (size_t)(k0 + cc)*HWP + gy*WW + x4;
            uint32_t dst = db + ((rr*32 + cc)*RST + 4 + x4) * 4;
            cp16(dst, src, ((unsigned)gy < HH) ? 16 : 0);
        }
        CP_COMMIT();
    };
    auto stage_wb = [&](int ck, int buf) {
        int k0 = ck * 32;
        for (int i = tid; i < 32*9; i += 256)
            wds[buf*384 + (i/9)*12 + (i%9)] = g_Wd[(k0 + i/9)*9 + (i%9)];
        for (int i = tid; i < CO*8; i += 256) {
            int oc = i >> 3, kg = i & 7;
            float4 v = *(const float4*)&g_Wpq[oc*CM + k0 + kg*4];
            v.x = totf32(v.x); v.y = totf32(v.y);
            v.z = totf32(v.z); v.w = totf32(v.w);
            *(float4*)&Bs[buf*(CO*KSTR) + oc*KSTR + kg*4] = v;
        }
    };

    float acc[4][NT][4];
#pragma unroll
    for (int mt = 0; mt < 4; mt++)
#pragma unroll
        for (int nt = 0; nt < NT; nt++)
#pragma unroll
            for (int i = 0; i < 4; i++) acc[mt][nt][i] = 0.f;

    stage_raw(0, 0); stage_wb(0, 0);

    for (int ck = 0; ck < 4; ck++) {
        int cur = ck & 1;
        if (ck < 3) { stage_raw(ck + 1, cur ^ 1); stage_wb(ck + 1, cur ^ 1); }
        if (ck < 3) cp_wait<1>(); else cp_wait<0>();
        __syncthreads();                       // S1: raw/Bs/wds[cur] ready

        // depthwise: thread -> 8 tasks of (1 ch, 4 px); STS.128 into As[k][px]
        const float* rb = raw + cur*RAWC;
        const float* wb = wds + cur*384;
#pragma unroll
        for (int v = 0; v < 8; v++) {
            int i  = tid + 256*v;
            int cc = i >> 6, q = i & 63;
            int yy = q >> 5, x = (q & 31) * 4;
            float4 a4 = make_float4(0.f, 0.f, 0.f, 0.f);
#pragma unroll
            for (int rr = 0; rr < 3; rr++) {
                const float* rp = rb + ((yy + rr)*32 + cc)*RST + 4 + x;
                float4 f = *(const float4*)rp;
                float xl = rp[-1], xr = rp[4];
                float w0 = wb[cc*12 + rr*3], w1 = wb[cc*12 + rr*3 + 1],
                      w2 = wb[cc*12 + rr*3 + 2];
                a4.x += w0*xl  + w1*f.x + w2*f.y;
                a4.y += w0*f.x + w1*f.y + w2*f.z;
                a4.z += w0*f.y + w1*f.z + w2*f.w;
                a4.w += w0*f.z + w1*f.w + w2*xr;
            }
            *(float4*)&As[cc*PSTR + yy*128 + x] =
                make_float4(totf32(a4.x), totf32(a4.y),
                            totf32(a4.z), totf32(a4.w));
        }
        __syncthreads();                       // S2: As ready

        const float* Bc = Bs + cur*(CO*KSTR);
#pragma unroll
        for (int ks = 0; ks < 4; ks++) {
            int kk = ks * 8;
            uint32_t a[4][4], bf[NT][2];
#pragma unroll
            for (int mt = 0; mt < 4; mt++) {
                int row = wpx + mt*16 + r;
                a[mt][0] = __float_as_uint(As[(kk+c  )*PSTR + row    ]);
                a[mt][1] = __float_as_uint(As[(kk+c  )*PSTR + row + 8]);
                a[mt][2] = __float_as_uint(As[(kk+c+4)*PSTR + row    ]);
                a[mt][3] = __float_as_uint(As[(kk+c+4)*PSTR + row + 8]);
            }
#pragma unroll
            for (int nt = 0; nt < NT; nt++) {
                int oc = woc + nt*8 + r;
                bf[nt][0] = __float_as_uint(Bc[oc*KSTR + kk + c    ]);
                bf[nt][1] = __float_as_uint(Bc[oc*KSTR + kk + c + 4]);
            }
#pragma unroll
            for (int mt = 0; mt < 4; mt++)
#pragma unroll
                for (int nt = 0; nt < NT; nt++)
                    mma16n8k8(acc[mt][nt], a[mt], bf[nt]);
        }
    }

    // epilogue: transpose via smem (raw region free) -> coalesced stores
    __syncthreads();
    float* sOut = dsm;                        // [80][256] = 20480 floats
#pragma unroll
    for (int mt = 0; mt < 4; mt++) {
        int row = wpx + mt*16 + r;
#pragma unroll
        for (int nt = 0; nt < NT; nt++) {
            int col = woc + nt*8 + c*2;
            sOut[(col  )*256 + row    ] = acc[mt][nt][0];
            sOut[(col+1)*256 + row    ] = acc[mt][nt][1];
            sOut[(col  )*256 + row + 8] = acc[mt][nt][2];
            sOut[(col+1)*256 + row + 8] = acc[mt][nt][3];
        }
    }
    __syncthreads();

    size_t ob = (size_t)b * OUTC * HWP + (size_t)y0 * WW;
    for (int i = tid; i < CO*64; i += 256) {
        int oc = i >> 6, p4 = (i & 63) * 4;
        float bi = sb[oc];
        float4 v = *(float4*)&sOut[oc*256 + p4];
        v.x = fmaxf(v.x + bi, 0.f); v.y = fmaxf(v.y + bi, 0.f);
        v.z = fmaxf(v.z + bi, 0.f); v.w = fmaxf(v.w + bi, 0.f);
        *(float4*)&out[ob + (size_t)oc*HWP + p4] = v;
    }
}

// ---------------------------------------------------------------------------
extern "C" void kernel_launch(void* const* d_in, const int* in_sizes, int n_in,
                              void* d_out, int out_size) {
    const float* flow = (const float*)d_in[0];
    const float* corr = (const float*)d_in[1];
    const float* Wc1  = (const float*)d_in[2];
    const float* bc1  = (const float*)d_in[3];
    const float* bf1  = (const float*)d_in[5];
    const float* bf2  = (const float*)d_in[7];
    const float* bp   = (const float*)d_in[10];
    float* out = (float*)d_out;

    const int PWDW_SMEM =
        (2*RAWC + 32*PSTR + 2*CO*KSTR + 2*32*12 + CO) * 4;
    cudaFuncSetAttribute(pwdw_kernel,
                         cudaFuncAttributeMaxDynamicSharedMemorySize, PWDW_SMEM);

    quant_kernel<<<5, 1024>>>(Wc1, (const float*)d_in[4], (const float*)d_in[6],
                              (const float*)d_in[8], (const float*)d_in[9]);
    convflo_kernel<<<dim3(HWP/128 + HWP/256, BB), 256>>>(corr, bc1, flow,
                                                         bf1, bf2, out);
    pwdw_kernel<<<dim3(HH/2, BB), 256, PWDW_SMEM>>>(bp, out);
}

// round 8
// speedup vs baseline: 3.1755x; 1.0311x over previous
#include <cuda_runtime.h>
#include <cstdint>

#define BB 16
#define HH 96
#define WW 128
#define HWP (HH*WW)        // 12288
#define CP 196
#define C1 96
#define CF1 64
#define CF2 32
#define CM 128
#define CO 80
#define OUTC 82
#define KSTR 36
#define ASTR 136           // conv1 As pixel-row stride per k (128+8)

// ---- scratch + quantized weights (device globals) -------------------------
__device__ float g_corflo[(size_t)BB*CM*HWP];   // [B,128,H,W]
__device__ float g_Wc1q[C1*CP];                 // fake-quant + tf32-rounded
__device__ float g_Wf1[CF1*2];
__device__ float g_Wf2[CF2*CF1];
__device__ float g_Wd[CM*9];
__device__ float g_Wpq[CO*CM];                  // fake-quant + tf32-rounded

__device__ __forceinline__ float totf32(float x) {   // round-to-nearest tf32
    float r; asm("cvt.rna.tf32.f32 %0, %1;" : "=f"(r) : "f"(x)); return r;
}
__device__ __forceinline__ void mma16n8k8(float* d, const uint32_t* a,
                                          const uint32_t* b) {
    asm volatile(
        "mma.sync.aligned.m16n8k8.row.col.f32.tf32.tf32.f32 "
        "{%0,%1,%2,%3}, {%4,%5,%6,%7}, {%8,%9}, {%0,%1,%2,%3};"
        : "+f"(d[0]), "+f"(d[1]), "+f"(d[2]), "+f"(d[3])
        : "r"(a[0]), "r"(a[1]), "r"(a[2]), "r"(a[3]), "r"(b[0]), "r"(b[1]));
}
__device__ __forceinline__ uint32_t smem_u32(const void* p) {
    uint32_t a;
    asm("{ .reg .u64 t; cvta.to.shared.u64 t, %1; cvt.u32.u64 %0, t; }"
        : "=r"(a) : "l"(p));
    return a;
}
__device__ __forceinline__ void cp16(uint32_t dst, const void* src, int sz) {
    asm volatile("cp.async.ca.shared.global [%0], [%1], 16, %2;"
                 :: "r"(dst), "l"(src), "r"(sz) : "memory");
}
#define CP_COMMIT() asm volatile("cp.async.commit_group;" ::: "memory")
template<int N> __device__ __forceinline__ void cp_wait() {
    asm volatile("cp.async.wait_group %0;" :: "n"(N) : "memory");
}

// ---------------------------------------------------------------------------
// Per-tensor symmetric int8 fake-quant; GEMM weights also tf32-pre-rounded.
// ---------------------------------------------------------------------------
__global__ void quant_kernel(const float* __restrict__ Wc1,
                             const float* __restrict__ Wf1,
                             const float* __restrict__ Wf2,
                             const float* __restrict__ Wd,
                             const float* __restrict__ Wp) {
    __shared__ float smax[1024];
    __shared__ float sscale;
    int t = blockIdx.x;
    const float* src; int n;
    if (t == 0)      { src = Wc1; n = C1*CP;   }
    else if (t == 1) { src = Wf1; n = CF1*2;   }
    else if (t == 2) { src = Wf2; n = CF2*CF1; }
    else if (t == 3) { src = Wd;  n = CM*9;    }
    else             { src = Wp;  n = CO*CM;   }

    float m = 0.f;
    for (int i = threadIdx.x; i < n; i += 1024) m = fmaxf(m, fabsf(src[i]));
    smax[threadIdx.x] = m;
    __syncthreads();
    for (int s = 512; s > 0; s >>= 1) {
        if (threadIdx.x < s)
            smax[threadIdx.x] = fmaxf(smax[threadIdx.x], smax[threadIdx.x + s]);
        __syncthreads();
    }
    if (threadIdx.x == 0) sscale = fmaxf(smax[0], 1e-8f) / 127.f;
    __syncthreads();
    float sc = sscale, inv = 1.f / sc;

    for (int i = threadIdx.x; i < n; i += 1024) {
        float q = rintf(src[i] * inv);
        q = fminf(fmaxf(q, -127.f), 127.f) * sc;
        if (t == 0)      g_Wc1q[i] = totf32(q);
        else if (t == 1) g_Wf1[i] = q;
        else if (t == 2) g_Wf2[i] = q;
        else if (t == 3) g_Wd[i]  = q;
        else             g_Wpq[i] = totf32(q);
    }
}

// ---------------------------------------------------------------------------
// Merged kernel: blocks x<96 run conv1 (tf32 GEMM, cp.async double buffer);
// blocks x>=96 run the flow MLP.
// conv1: As[k][px] (ASTR=136) staged straight from corr via cp.async;
// Bs[oc][k] (KSTR=36) from pre-rounded g_Wc1q. A-frag tf32 cvt at load.
// ---------------------------------------------------------------------------
__global__ void __launch_bounds__(256)
convflo_kernel(const float* __restrict__ corr, const float* __restrict__ bc1,
               const float* __restrict__ flow, const float* __restrict__ bf1,
               const float* __restrict__ bf2, float* __restrict__ out) {
    extern __shared__ __align__(16) float dsm[];
    int tid = threadIdx.x;
    int b   = blockIdx.y;

    if (blockIdx.x >= HWP/128) {
        // ---------------- flo part ----------------
        float* sW1 = dsm;
        float* sb1 = sW1 + CF1*2;
        float* sW2 = sb1 + CF1;
        float* sb2 = sW2 + CF2*CF1;
        for (int i = tid; i < CF1*2;   i += 256) sW1[i] = g_Wf1[i];
        for (int i = tid; i < CF1;     i += 256) sb1[i] = bf1[i];
        for (int i = tid; i < CF2*CF1; i += 256) sW2[i] = g_Wf2[i];
        for (int i = tid; i < CF2;     i += 256) sb2[i] = bf2[i];
        __syncthreads();

        int px = (blockIdx.x - HWP/128) * 256 + tid;
        float f0 = flow[((size_t)b*2 + 0)*HWP + px];
        float f1 = flow[((size_t)b*2 + 1)*HWP + px];

        float hid[CF1];
#pragma unroll
        for (int h = 0; h < CF1; h++)
            hid[h] = fmaxf(f0*sW1[h*2] + f1*sW1[h*2+1] + sb1[h], 0.f);
#pragma unroll
        for (int o = 0; o < CF2; o++) {
            float a = sb2[o];
#pragma unroll
            for (int h = 0; h < CF1; h++) a += hid[h] * sW2[o*CF1 + h];
            g_corflo[((size_t)(b*CM + C1 + o))*HWP + px] = fmaxf(a, 0.f);
        }
        out[((size_t)(b*OUTC + 80))*HWP + px] = f0;
        out[((size_t)(b*OUTC + 81))*HWP + px] = f1;
        return;
    }

    // ---------------- conv1: 128px x 96oc tf32 GEMM ----------------
    constexpr int NCH = (CP + 31) / 32;     // 7
    constexpr int NT  = C1 / 16;            // 6
    float* As = dsm;                        // [2][32*ASTR]
    float* Bs = dsm + 2*32*ASTR;            // [2][96*KSTR]
    uint32_t asb = smem_u32(As), bsb = smem_u32(Bs);

    int wid  = tid >> 5, lane = tid & 31;
    int r    = lane >> 2, c = lane & 3;
    int wpx  = (wid & 3) * 32;
    int woc  = (wid >> 2) * (C1 / 2);
    int px0  = blockIdx.x * 128;
    const float* Xb = corr + (size_t)b * CP * HWP + px0;

    auto stage = [&](int ck, int buf) {
        int k0 = ck * 32;
        // A: 32 k-rows x 128 px = 1024 cp16 -> 4 per thread
#pragma unroll
        for (int v = 0; v < 4; v++) {
            int i  = tid + 256*v;
            int kk = i >> 5, xi = i & 31;
            int k  = k0 + kk;
            cp16(asb + (uint32_t)(buf*32*ASTR + kk*ASTR + xi*4)*4,
                 Xb + (size_t)k*HWP + xi*4, (k < CP) ? 16 : 0);
        }
        // B: 96 oc x 8 kg = 768 cp16 -> 3 per thread
#pragma unroll
        for (int v = 0; v < 3; v++) {
            int i = tid + 256*v;
            int oc = i >> 3, kg = i & 7;
            int kb = k0 + kg*4;
            cp16(bsb + (uint32_t)(buf*C1*KSTR + oc*KSTR + kg*4)*4,
                 &g_Wc1q[oc*CP + kb], (kb < CP) ? 16 : 0);
        }
        CP_COMMIT();
    };

    float acc[2][NT][4];
#pragma unroll
    for (int mt = 0; mt < 2; mt++)
#pragma unroll
        for (int nt = 0; nt < NT; nt++)
#pragma unroll
            for (int i = 0; i < 4; i++) acc[mt][nt][i] = 0.f;

    stage(0, 0);

    for (int ch = 0; ch < NCH; ch++) {
        int cur = ch & 1;
        if (ch + 1 < NCH) { stage(ch + 1, cur ^ 1); cp_wait<1>(); }
        else              { cp_wait<0>(); }
        __syncthreads();                       // staged[cur] ready

        const float* Ac = As + cur*32*ASTR;
        const float* Bc = Bs + cur*C1*KSTR;
#pragma unroll
        for (int ks = 0; ks < 4; ks++) {
            int kk = ks * 8;
            uint32_t a[2][4], bf[NT][2];
#pragma unroll
            for (int mt = 0; mt < 2; mt++) {
                int row = wpx + mt*16 + r;
                a[mt][0] = __float_as_uint(totf32(Ac[(kk+c  )*ASTR + row    ]));
                a[mt][1] = __float_as_uint(totf32(Ac[(kk+c  )*ASTR + row + 8]));
                a[mt][2] = __float_as_uint(totf32(Ac[(kk+c+4)*ASTR + row    ]));
                a[mt][3] = __float_as_uint(totf32(Ac[(kk+c+4)*ASTR + row + 8]));
            }
#pragma unroll
            for (int nt = 0; nt < NT; nt++) {
                int oc = woc + nt*8 + r;
                bf[nt][0] = __float_as_uint(Bc[oc*KSTR + kk + c    ]);
                bf[nt][1] = __float_as_uint(Bc[oc*KSTR + kk + c + 4]);
            }
#pragma unroll
            for (int mt = 0; mt < 2; mt++)
#pragma unroll
                for (int nt = 0; nt < NT; nt++)
                    mma16n8k8(acc[mt][nt], a[mt], bf[nt]);
        }
        __syncthreads();                       // compute[cur] done -> reusable
    }

    // epilogue: transpose through smem -> coalesced channel-major stores
    float* sOut = dsm;                         // [96][128]
#pragma unroll
    for (int mt = 0; mt < 2; mt++) {
        int row = wpx + mt*16 + r;
#pragma unroll
        for (int nt = 0; nt < NT; nt++) {
            int col = woc + nt*8 + c*2;
            sOut[(col  )*128 + row    ] = acc[mt][nt][0];
            sOut[(col+1)*128 + row    ] = acc[mt][nt][1];
            sOut[(col  )*128 + row + 8] = acc[mt][nt][2];
            sOut[(col+1)*128 + row + 8] = acc[mt][nt][3];
        }
    }
    __syncthreads();

    size_t ob = (size_t)b * CM * HWP + px0;
    for (int i = tid; i < C1*32; i += 256) {
        int oc = i >> 5, p4 = (i & 31) * 4;
        float bi = bc1[oc];
        float4 v = *(float4*)&sOut[oc*128 + p4];
        v.x = fmaxf(v.x + bi, 0.f); v.y = fmaxf(v.y + bi, 0.f);
        v.z = fmaxf(v.z + bi, 0.f); v.w = fmaxf(v.w + bi, 0.f);
        *(float4*)&g_corflo[ob + (size_t)oc*HWP + p4] = v;
    }
}

// ---------------------------------------------------------------------------
// Fused depthwise-3x3 + pointwise 128->80 tf32 GEMM, 2 rows per block.
// cp.async double-buffered halo staging; As in [k][px] (PSTR=264).
// ---------------------------------------------------------------------------
#define RST  136                 // raw row stride (halo at [3],[132], data 4+x)
#define RAWC (4*32*RST)          // 4 rows x 32 ch per chunk = 17408 floats
#define PSTR 264                 // As pixel stride (256 + 8)
__global__ void __launch_bounds__(256)
pwdw_kernel(const float* __restrict__ bp, float* __restrict__ out) {
    extern __shared__ __align__(16) float dsm[];
    float* raw = dsm;                     // [2][RAWC]
    float* As  = dsm + 2*RAWC;            // [32][PSTR]
    float* Bs  = As  + 32*PSTR;           // [2][80*KSTR]
    float* wds = Bs  + 2*CO*KSTR;         // [2][32*12]
    float* sb  = wds + 2*32*12;           // [80]

    constexpr int NT = CO / 16;           // 5
    int tid = threadIdx.x;
    int wid = tid >> 5, lane = tid & 31;
    int r   = lane >> 2, c = lane & 3;
    int wpx = (wid & 3) * 64;
    int woc = (wid >> 2) * (CO / 2);
    int y0  = blockIdx.x * 2;
    int b   = blockIdx.y;

    for (int i = tid; i < 2*128; i += 256) {   // zero x-halos (stay zero)
        int o = (i >> 7) * RAWC + (i & 127) * RST;
        raw[o + 3] = 0.f; raw[o + 132] = 0.f;
    }
    for (int i = tid; i < CO; i += 256) sb[i] = bp[i];

    uint32_t rawb = smem_u32(raw);
    const float* cfb = g_corflo + (size_t)b * CM * HWP;

    auto stage_raw = [&](int ck, int buf) {
        int k0 = ck * 32;
        uint32_t db = rawb + (uint32_t)buf * RAWC * 4;
#pragma unroll
        for (int v = 0; v < 16; v++) {
            int i = tid + 256*v;
            int rr = i >> 10, rem = i & 1023;
            int cc = rem >> 5, x4 = (rem & 31) * 4;
            int gy = y0 - 1 + rr;
            cp16(db + ((rr*32 + cc)*RST + 4 + x4) * 4,
                 cfb + (size_t)(k0 + cc)*HWP + gy*WW + x4,
                 ((unsigned)gy < HH) ? 16 : 0);
        }
        CP_COMMIT();
    };
    auto stage_wb = [&](int ck, int buf) {
        int k0 = ck * 32;
        for (int i = tid; i < 32*9; i += 256)
            wds[buf*384 + (i/9)*12 + (i%9)] = g_Wd[(k0 + i/9)*9 + (i%9)];
        for (int i = tid; i < CO*8; i += 256) {
            int oc = i >> 3, kg = i & 7;
            *(float4*)&Bs[buf*(CO*KSTR) + oc*KSTR + kg*4] =
                *(const float4*)&g_Wpq[oc*CM + k0 + kg*4];   // pre-rounded
        }
    };

    float acc[4][NT][4];
#pragma unroll
    for (int mt = 0; mt < 4; mt++)
#pragma unroll
        for (int nt = 0; nt < NT; nt++)
#pragma unroll
            for (int i = 0; i < 4; i++) acc[mt][nt][i] = 0.f;

    stage_raw(0, 0); stage_wb(0, 0);

    for (int ck = 0; ck < 4; ck++) {
        int cur = ck & 1;
        if (ck < 3) { stage_raw(ck + 1, cur ^ 1); stage_wb(ck + 1, cur ^ 1); }
        if (ck < 3) cp_wait<1>(); else cp_wait<0>();
        __syncthreads();                       // S1: raw/Bs/wds[cur] ready

        const float* rb = raw + cur*RAWC;
        const float* wb = wds + cur*384;
#pragma unroll
        for (int v = 0; v < 8; v++) {
            int i  = tid + 256*v;
            int cc = i >> 6, q = i & 63;
            int yy = q >> 5, x = (q & 31) * 4;
            float4 a4 = make_float4(0.f, 0.f, 0.f, 0.f);
#pragma unroll
            for (int rr = 0; rr < 3; rr++) {
                const float* rp = rb + ((yy + rr)*32 + cc)*RST + 4 + x;
                float4 f = *(const float4*)rp;
                float xl = rp[-1], xr = rp[4];
                float w0 = wb[cc*12 + rr*3], w1 = wb[cc*12 + rr*3 + 1],
                      w2 = wb[cc*12 + rr*3 + 2];
                a4.x += w0*xl  + w1*f.x + w2*f.y;
                a4.y += w0*f.x + w1*f.y + w2*f.z;
                a4.z += w0*f.y + w1*f.z + w2*f.w;
                a4.w += w0*f.z + w1*f.w + w2*xr;
            }
            *(float4*)&As[cc*PSTR + yy*128 + x] =
                make_float4(totf32(a4.x), totf32(a4.y),
                            totf32(a4.z), totf32(a4.w));
        }
        __syncthreads();                       // S2: As ready

        const float* Bc = Bs + cur*(CO*KSTR);
#pragma unroll
        for (int ks = 0; ks < 4; ks++) {
            int kk = ks * 8;
            uint32_t a[4][4], bf[NT][2];
#pragma unroll
            for (int mt = 0; mt < 4; mt++) {
                int row = wpx + mt*16 + r;
                a[mt][0] = __float_as_uint(As[(kk+c  )*PSTR + row    ]);
                a[mt][1] = __float_as_uint(As[(kk+c  )*PSTR + row + 8]);
                a[mt][2] = __float_as_uint(As[(kk+c+4)*PSTR + row    ]);
                a[mt][3] = __float_as_uint(As[(kk+c+4)*PSTR + row + 8]);
            }
#pragma unroll
            for (int nt = 0; nt < NT; nt++) {
                int oc = woc + nt*8 + r;
                bf[nt][0] = __float_as_uint(Bc[oc*KSTR + kk + c    ]);
                bf[nt][1] = __float_as_uint(Bc[oc*KSTR + kk + c + 4]);
            }
#pragma unroll
            for (int mt = 0; mt < 4; mt++)
#pragma unroll
                for (int nt = 0; nt < NT; nt++)
                    mma16n8k8(acc[mt][nt], a[mt], bf[nt]);
        }
        __syncthreads();       // S3: compute[cur] done -> buffers reusable
    }

    // epilogue: transpose via smem (raw region free) -> coalesced stores
    float* sOut = dsm;                        // [80][256]
#pragma unroll
    for (int mt = 0; mt < 4; mt++) {
        int row = wpx + mt*16 + r;
#pragma unroll
        for (int nt = 0; nt < NT; nt++) {
            int col = woc + nt*8 + c*2;
            sOut[(col  )*256 + row    ] = acc[mt][nt][0];
            sOut[(col+1)*256 + row    ] = acc[mt][nt][1];
            sOut[(col  )*256 + row + 8] = acc[mt][nt][2];
            sOut[(col+1)*256 + row + 8] = acc[mt][nt][3];
        }
    }
    __syncthreads();

    size_t ob = (size_t)b * OUTC * HWP + (size_t)y0 * WW;
    for (int i = tid; i < CO*64; i += 256) {
        int oc = i >> 6, p4 = (i & 63) * 4;
        float bi = sb[oc];
        float4 v = *(float4*)&sOut[oc*256 + p4];
        v.x = fmaxf(v.x + bi, 0.f); v.y = fmaxf(v.y + bi, 0.f);
        v.z = fmaxf(v.z + bi, 0.f); v.w = fmaxf(v.w + bi, 0.f);
        *(float4*)&out[ob + (size_t)oc*HWP + p4] = v;
    }
}

// ---------------------------------------------------------------------------
extern "C" void kernel_launch(void* const* d_in, const int* in_sizes, int n_in,
                              void* d_out, int out_size) {
    const float* flow = (const float*)d_in[0];
    const float* corr = (const float*)d_in[1];
    const float* Wc1  = (const float*)d_in[2];
    const float* bc1  = (const float*)d_in[3];
    const float* bf1  = (const float*)d_in[5];
    const float* bf2  = (const float*)d_in[7];
    const float* bp   = (const float*)d_in[10];
    float* out = (float*)d_out;

    const int CONV_SMEM = (2*32*ASTR + 2*C1*KSTR) * 4;   // 62464 B
    const int PWDW_SMEM =
        (2*RAWC + 32*PSTR + 2*CO*KSTR + 2*32*12 + CO) * 4;
    cudaFuncSetAttribute(convflo_kernel,
                         cudaFuncAttributeMaxDynamicSharedMemorySize, CONV_SMEM);
    cudaFuncSetAttribute(pwdw_kernel,
                         cudaFuncAttributeMaxDynamicSharedMemorySize, PWDW_SMEM);

    quant_kernel<<<5, 1024>>>(Wc1, (const float*)d_in[4], (const float*)d_in[6],
                              (const float*)d_in[8], (const float*)d_in[9]);
    convflo_kernel<<<dim3(HWP/128 + HWP/256, BB), 256, CONV_SMEM>>>(
        corr, bc1, flow, bf1, bf2, out);
    pwdw_kernel<<<dim3(HH/2, BB), 256, PWDW_SMEM>>>(bp, out);
}

// round 9
// speedup vs baseline: 3.3831x; 1.0654x over previous
#include <cuda_runtime.h>
#include <cuda_fp16.h>
#include <cstdint>

#define BB 16
#define HH 96
#define WW 128
#define HWP 12288
#define CP 196
#define C1 96
#define CF1 64
#define CF2 32
#define CM 128
#define CO 80
#define OUTC 82

// ---- globals (no allocation allowed) --------------------------------------
__device__ __align__(16) __half g_corflo[(size_t)BB*CM*HWP];  // fp16 cor_flo
__device__ __align__(16) float g_Wc1q[C1*CP];   // fake-quant + tf32-rounded
__device__ __align__(16) float g_Wf1[CF1*2];
__device__ __align__(16) float g_Wf2[CF2*CF1];
__device__ __align__(16) float g_Wd[CM*9];
__device__ __align__(16) float g_Wpq[CO*CM];    // fake-quant + tf32-rounded

__device__ __forceinline__ float totf32(float x) {
    float r; asm("cvt.rna.tf32.f32 %0, %1;" : "=f"(r) : "f"(x)); return r;
}
__device__ __forceinline__ void mma16n8k8(float* d, const uint32_t* a,
                                          const uint32_t* b) {
    asm volatile(
        "mma.sync.aligned.m16n8k8.row.col.f32.tf32.tf32.f32 "
        "{%0,%1,%2,%3}, {%4,%5,%6,%7}, {%8,%9}, {%0,%1,%2,%3};"
        : "+f"(d[0]), "+f"(d[1]), "+f"(d[2]), "+f"(d[3])
        : "r"(a[0]), "r"(a[1]), "r"(a[2]), "r"(a[3]), "r"(b[0]), "r"(b[1]));
}
__device__ __forceinline__ uint32_t smem_u32(const void* p) {
    uint32_t a;
    asm("{ .reg .u64 t; cvta.to.shared.u64 t, %1; cvt.u32.u64 %0, t; }"
        : "=r"(a) : "l"(p));
    return a;
}
// one bulk async copy: global -> shared, completion via mbarrier tx bytes
__device__ __forceinline__ void bulk_g2s(uint32_t dst, const void* src,
                                         uint32_t bytes, uint32_t mbar) {
    asm volatile(
        "cp.async.bulk.shared::cluster.global.mbarrier::complete_tx::bytes "
        "[%0], [%1], %2, [%3];"
        :: "r"(dst), "l"(src), "r"(bytes), "r"(mbar) : "memory");
}
#define MBAR_INIT(mb, c) \
    asm volatile("mbarrier.init.shared.b64 [%0], %1;" :: "r"(mb), "r"(c) : "memory")
#define MBAR_EXPECT_TX(mb, bytes) \
    asm volatile("mbarrier.arrive.expect_tx.shared.b64 _, [%0], %1;" \
                 :: "r"(mb), "r"((uint32_t)(bytes)) : "memory")
#define MBAR_WAIT(mb, ph) do {                                               \
    asm volatile("{\n\t.reg .pred P1;\n\t"                                   \
        "WL%=:\n\tmbarrier.try_wait.parity.acquire.cta.shared::cta.b64 "     \
        "P1, [%0], %1, 0x989680;\n\t"                                        \
        "@P1 bra.uni WD%=;\n\tbra.uni WL%=;\n\tWD%=:\n\t}"                   \
        :: "r"(mb), "r"((uint32_t)(ph)) : "memory"); } while (0)

// ---------------------------------------------------------------------------
// Per-tensor symmetric int8 fake-quant; GEMM weights tf32-pre-rounded.
// ---------------------------------------------------------------------------
__global__ void quant_kernel(const float* __restrict__ Wc1,
                             const float* __restrict__ Wf1,
                             const float* __restrict__ Wf2,
                             const float* __restrict__ Wd,
                             const float* __restrict__ Wp) {
    __shared__ float smax[1024];
    __shared__ float sscale;
    int t = blockIdx.x;
    const float* src; int n;
    if (t == 0)      { src = Wc1; n = C1*CP;   }
    else if (t == 1) { src = Wf1; n = CF1*2;   }
    else if (t == 2) { src = Wf2; n = CF2*CF1; }
    else if (t == 3) { src = Wd;  n = CM*9;    }
    else             { src = Wp;  n = CO*CM;   }

    float m = 0.f;
    for (int i = threadIdx.x; i < n; i += 1024) m = fmaxf(m, fabsf(src[i]));
    smax[threadIdx.x] = m;
    __syncthreads();
    for (int s = 512; s > 0; s >>= 1) {
        if (threadIdx.x < s)
            smax[threadIdx.x] = fmaxf(smax[threadIdx.x], smax[threadIdx.x + s]);
        __syncthreads();
    }
    if (threadIdx.x == 0) sscale = fmaxf(smax[0], 1e-8f) / 127.f;
    __syncthreads();
    float sc = sscale, inv = 1.f / sc;

    for (int i = threadIdx.x; i < n; i += 1024) {
        float q = rintf(src[i] * inv);
        q = fminf(fmaxf(q, -127.f), 127.f) * sc;
        if (t == 0)      g_Wc1q[i] = totf32(q);
        else if (t == 1) g_Wf1[i] = q;
        else if (t == 2) g_Wf2[i] = q;
        else if (t == 3) g_Wd[i]  = q;
        else             g_Wpq[i] = totf32(q);
    }
}

// ---------------------------------------------------------------------------
// convflo: blocks x<48 = conv1 (256px x 96oc tf32 GEMM, cp.async.bulk
// double-buffered A, resident B); blocks x>=48 = flow MLP.
// ---------------------------------------------------------------------------
#define C1_ASTR 264
#define C1_BSTR 228
#define C1_AS_F (2*32*C1_ASTR)          // 16896 floats
#define C1_BS_F (C1*C1_BSTR)            // 21888 floats

__global__ void __launch_bounds__(512)
convflo_kernel(const float* __restrict__ corr, const float* __restrict__ bc1,
               const float* __restrict__ flow, const float* __restrict__ bf1,
               const float* __restrict__ bf2, float* __restrict__ out) {
    extern __shared__ __align__(16) float dsm[];
    int tid = threadIdx.x;
    int b   = blockIdx.y;

    if (blockIdx.x >= 48) {
        // ---------------- flo part ----------------
        float* sW1 = dsm;               // 128
        float* sb1 = dsm + 128;         // 64
        float* sW2 = dsm + 192;         // 2048
        float* sb2 = dsm + 2240;        // 32
        for (int i = tid; i < CF1*2;   i += 512) sW1[i] = g_Wf1[i];
        for (int i = tid; i < CF1;     i += 512) sb1[i] = bf1[i];
        for (int i = tid; i < CF2*CF1; i += 512) sW2[i] = g_Wf2[i];
        for (int i = tid; i < CF2;     i += 512) sb2[i] = bf2[i];
        __syncthreads();

        int px = (blockIdx.x - 48) * 512 + tid;
        float f0 = flow[((size_t)b*2 + 0)*HWP + px];
        float f1 = flow[((size_t)b*2 + 1)*HWP + px];

        float hid[CF1];
#pragma unroll
        for (int h = 0; h < CF1; h++)
            hid[h] = fmaxf(f0*sW1[h*2] + f1*sW1[h*2+1] + sb1[h], 0.f);
#pragma unroll
        for (int o = 0; o < CF2; o++) {
            float a = sb2[o];
#pragma unroll
            for (int h = 0; h < CF1; h++) a += hid[h] * sW2[o*CF1 + h];
            g_corflo[((size_t)(b*CM + C1 + o))*HWP + px] =
                __float2half(fmaxf(a, 0.f));
        }
        out[((size_t)(b*OUTC + 80))*HWP + px] = f0;
        out[((size_t)(b*OUTC + 81))*HWP + px] = f1;
        return;
    }

    // ---------------- conv1 ----------------
    float* As = dsm;                     // [2][32][264]
    float* Bs = dsm + C1_AS_F;           // [96][228]
    unsigned long long* mb = (unsigned long long*)(dsm + C1_AS_F + C1_BS_F);
    uint32_t asb = smem_u32(As), bsb = smem_u32(Bs);
    uint32_t mb0 = smem_u32(&mb[0]), mb1 = smem_u32(&mb[1]);

    int wid = tid >> 5, lane = tid & 31;
    int r = lane >> 2, c = lane & 3;
    int wpx = (wid & 3) * 64;            // 4 px-groups x 64 px
    int woc = (wid >> 2) * 24;           // 4 oc-groups x 24 oc
    int px0 = blockIdx.x * 256;
    const float* Xb = corr + (size_t)b * CP * HWP + px0;

    if (tid == 0) { MBAR_INIT(mb0, 1); MBAR_INIT(mb1, 1); }
    // zero Bs cols 196..227 (bulk writes only cols 0..195)
    for (int i = tid; i < C1*8; i += 512) {
        int oc = i >> 3, j = i & 7;
        *(float4*)&Bs[oc*C1_BSTR + 196 + j*4] = make_float4(0.f,0.f,0.f,0.f);
    }
    float bias[3][2];
#pragma unroll
    for (int nt = 0; nt < 3; nt++) {
        bias[nt][0] = bc1[woc + nt*8 + c*2];
        bias[nt][1] = bc1[woc + nt*8 + c*2 + 1];
    }
    __syncthreads();

    // prologue: chunk0 (A + all B) -> stage0, chunk1 -> stage1
    if (tid == 0) {
        MBAR_EXPECT_TX(mb0, 32*1024 + C1*784);
        MBAR_EXPECT_TX(mb1, 32*1024);
    }
    if (tid < 32) {
        bulk_g2s(asb + (uint32_t)(tid*C1_ASTR)*4, Xb + (size_t)tid*HWP,
                 1024, mb0);
    } else if (tid < 128) {
        int oc = tid - 32;
        bulk_g2s(bsb + (uint32_t)(oc*C1_BSTR)*4, g_Wc1q + oc*CP, 784, mb0);
    } else if (tid < 160) {
        int t2 = tid - 128;
        bulk_g2s(asb + (uint32_t)((32 + t2)*C1_ASTR)*4,
                 Xb + (size_t)(32 + t2)*HWP, 1024, mb1);
    }

    float acc[4][3][4];
#pragma unroll
    for (int mt = 0; mt < 4; mt++)
#pragma unroll
        for (int nt = 0; nt < 3; nt++)
#pragma unroll
            for (int i = 0; i < 4; i++) acc[mt][nt][i] = 0.f;

    int ph0 = 0, ph1 = 0;
    for (int ch = 0; ch < 7; ch++) {
        int s = ch & 1;
        if (s == 0) { MBAR_WAIT(mb0, ph0); ph0 ^= 1; }
        else        { MBAR_WAIT(mb1, ph1); ph1 ^= 1; }
        const float* Ac = As + s * 32 * C1_ASTR;

#pragma unroll
        for (int ks = 0; ks < 4; ks++) {
            int kloc = ks * 8;
            int kk = ch * 32 + kloc;
            if (kk >= CP) break;                 // only triggers at ch=6
            uint32_t a[4][4], bf[3][2];
#pragma unroll
            for (int mt = 0; mt < 4; mt++) {
                int row = wpx + mt*16 + r;
                a[mt][0] = __float_as_uint(totf32(Ac[(kloc+c  )*C1_ASTR + row    ]));
                a[mt][1] = __float_as_uint(totf32(Ac[(kloc+c  )*C1_ASTR + row + 8]));
                a[mt][2] = __float_as_uint(totf32(Ac[(kloc+c+4)*C1_ASTR + row    ]));
                a[mt][3] = __float_as_uint(totf32(Ac[(kloc+c+4)*C1_ASTR + row + 8]));
            }
#pragma unroll
            for (int nt = 0; nt < 3; nt++) {
                int oc = woc + nt*8 + r;
                bf[nt][0] = __float_as_uint(Bs[oc*C1_BSTR + kk + c    ]);
                bf[nt][1] = __float_as_uint(Bs[oc*C1_BSTR + kk + c + 4]);
            }
#pragma unroll
            for (int mt = 0; mt < 4; mt++)
#pragma unroll
                for (int nt = 0; nt < 3; nt++)
                    mma16n8k8(acc[mt][nt], a[mt], bf[nt]);
        }
        __syncthreads();                          // all reads of stage s done

        int nc = ch + 2;
        if (nc < 7) {
            int k0 = nc * 32;
            int nr = CP - k0; if (nr > 32) nr = 32;
            if (tid == 0) {
                if (s == 0) MBAR_EXPECT_TX(mb0, nr*1024);
                else        MBAR_EXPECT_TX(mb1, nr*1024);
            }
            if (tid < nr)
                bulk_g2s(asb + (uint32_t)((s*32 + tid)*C1_ASTR)*4,
                         Xb + (size_t)(k0 + tid)*HWP, 1024,
                         (s == 0) ? mb0 : mb1);
        }
    }

    // epilogue: direct fp16 stores (8 lanes same col -> 8 consecutive px)
    __half* cf = g_corflo + (size_t)b * CM * HWP + px0;
#pragma unroll
    for (int mt = 0; mt < 4; mt++) {
        int row = wpx + mt*16 + r;
#pragma unroll
        for (int nt = 0; nt < 3; nt++) {
            int col = woc + nt*8 + c*2;
            cf[(size_t)col*HWP + row] =
                __float2half(fmaxf(acc[mt][nt][0] + bias[nt][0], 0.f));
            cf[(size_t)(col+1)*HWP + row] =
                __float2half(fmaxf(acc[mt][nt][1] + bias[nt][1], 0.f));
            cf[(size_t)col*HWP + row + 8] =
                __float2half(fmaxf(acc[mt][nt][2] + bias[nt][0], 0.f));
            cf[(size_t)(col+1)*HWP + row + 8] =
                __float2half(fmaxf(acc[mt][nt][3] + bias[nt][1], 0.f));
        }
    }
}

// ---------------------------------------------------------------------------
// pwdw: fused depthwise-3x3 + pointwise 128->80 tf32 GEMM, 2 rows/block.
// fp16 halo staged via cp.async.bulk (double buffer); Bs/wds resident.
// ---------------------------------------------------------------------------
#define P_RSTH 144                       // halves per halo row (data at 8..135)
#define P_RAWH (4*32*P_RSTH)             // 18432 halves per buffer
#define P_ASTR 264
#define P_BSTR 132
#define P_AS_OFF 18432                   // float offsets into dsm
#define P_BS_OFF (P_AS_OFF + 32*P_ASTR)  // 26880
#define P_WD_OFF (P_BS_OFF + CO*P_BSTR)  // 37440
#define P_SB_OFF (P_WD_OFF + CM*12)      // 38976
#define P_MB_OFF (P_SB_OFF + CO)         // 39056

__global__ void __launch_bounds__(256)
pwdw_kernel(const float* __restrict__ bp, float* __restrict__ out) {
    extern __shared__ __align__(16) float dsm[];
    __half* raw = (__half*)dsm;                 // [2][P_RAWH]
    float* As  = dsm + P_AS_OFF;                // [32][264]
    float* Bs  = dsm + P_BS_OFF;                // [80][132]
    float* wds = dsm + P_WD_OFF;                // [128][12]
    float* sb  = dsm + P_SB_OFF;                // [80]
    unsigned long long* mb = (unsigned long long*)(dsm + P_MB_OFF);

    int tid = threadIdx.x;
    int wid = tid >> 5, lane = tid & 31;
    int r = lane >> 2, c = lane & 3;
    int wpx = (wid & 3) * 64;
    int woc = (wid >> 2) * 40;
    int y0 = blockIdx.x * 2;
    int b  = blockIdx.y;
    uint32_t rawb = smem_u32(raw);
    uint32_t mb0 = smem_u32(&mb[0]), mb1 = smem_u32(&mb[1]);
    const __half* cfb = g_corflo + (size_t)b * CM * HWP;

    if (tid == 0) { MBAR_INIT(mb0, 1); MBAR_INIT(mb1, 1); }
    for (int i = tid; i < CO; i += 256) sb[i] = bp[i];
    for (int i = tid; i < CM*9; i += 256) wds[(i/9)*12 + (i%9)] = g_Wd[i];
    // zero x-halo slots [7],[136] of every row, both buffers
    for (int i = tid; i < 2*128; i += 256) {
        int o = (i >> 7) * P_RAWH + (i & 127) * P_RSTH;
        raw[o + 7] = __float2half(0.f);
        raw[o + 136] = __float2half(0.f);
    }
    // zero OOB gy row (constant across chunks), both buffers
    int rinv = (y0 == 0) ? 0 : ((y0 == HH - 2) ? 3 : -1);
    if (rinv >= 0) {
        uint32_t* rz = (uint32_t*)raw;
        for (int i = tid; i < 2*32*72; i += 256) {
            int bu = i / (32*72), rem = i % (32*72);
            int cc = rem / 72, hw = rem % 72;
            rz[(bu*P_RAWH + (rinv*32 + cc)*P_RSTH)/2 + hw] = 0;
        }
    }
    int nv = 4 - (y0 == 0) - (y0 == HH - 2);
    uint32_t txA = (uint32_t)nv * 32 * 256;
    __syncthreads();

    // prologue: chunk0 halo + Bs -> mb0, chunk1 halo -> mb1
    if (tid == 0) {
        MBAR_EXPECT_TX(mb0, txA + CO*512);
        MBAR_EXPECT_TX(mb1, txA);
    }
    if (tid < 128) {
        int rr = tid >> 5, cc = tid & 31;
        int gy = y0 - 1 + rr;
        if ((unsigned)gy < HH) {
            bulk_g2s(rawb + (uint32_t)(((rr*32 + cc)*P_RSTH + 8)*2),
                     cfb + (size_t)cc*HWP + gy*WW, 256, mb0);
            bulk_g2s(rawb + (uint32_t)((P_RAWH + (rr*32 + cc)*P_RSTH + 8)*2),
                     cfb + (size_t)(32 + cc)*HWP + gy*WW, 256, mb1);
        }
    } else if (tid < 208) {
        int oc = tid - 128;
        bulk_g2s(smem_u32(Bs) + (uint32_t)(oc*P_BSTR)*4,
                 g_Wpq + oc*CM, 512, mb0);
    }

    float acc[4][5][4];
#pragma unroll
    for (int mt = 0; mt < 4; mt++)
#pragma unroll
        for (int nt = 0; nt < 5; nt++)
#pragma unroll
            for (int i = 0; i < 4; i++) acc[mt][nt][i] = 0.f;

    int ph0 = 0, ph1 = 0;
    for (int ck = 0; ck < 4; ck++) {
        int s = ck & 1;
        if (s == 0) { MBAR_WAIT(mb0, ph0); ph0 ^= 1; }
        else        { MBAR_WAIT(mb1, ph1); ph1 ^= 1; }

        // depthwise: fp16 halo -> fp32 -> tf32 A-tile
        const __half* rb = raw + s * P_RAWH;
        const float* wb = wds + ck * 32 * 12;
#pragma unroll
        for (int v = 0; v < 8; v++) {
            int i = tid + 256*v;
            int cc = i >> 6, q = i & 63;
            int yy = q >> 5, x = (q & 31) * 4;
            float4 a4 = make_float4(0.f, 0.f, 0.f, 0.f);
#pragma unroll
            for (int rr = 0; rr < 3; rr++) {
                const __half* rp = rb + ((yy + rr)*32 + cc)*P_RSTH + 8 + x;
                float2 f01 = __half22float2(*(const __half2*)rp);
                float2 f23 = __half22float2(*(const __half2*)(rp + 2));
                float xl = __half2float(rp[-1]);
                float xr = __half2float(rp[4]);
                const float* w = wb + cc*12 + rr*3;
                a4.x += w[0]*xl    + w[1]*f01.x + w[2]*f01.y;
                a4.y += w[0]*f01.x + w[1]*f01.y + w[2]*f23.x;
                a4.z += w[0]*f01.y + w[1]*f23.x + w[2]*f23.y;
                a4.w += w[0]*f23.x + w[1]*f23.y + w[2]*xr;
            }
            *(float4*)&As[cc*P_ASTR + yy*128 + x] =
                make_float4(totf32(a4.x), totf32(a4.y),
                            totf32(a4.z), totf32(a4.w));
        }
        __syncthreads();                       // As ready

#pragma unroll
        for (int ks = 0; ks < 4; ks++) {
            int kloc = ks * 8;
            int kk = ck * 32 + kloc;
            uint32_t a[4][4], bf[5][2];
#pragma unroll
            for (int mt = 0; mt < 4; mt++) {
                int row = wpx + mt*16 + r;
                a[mt][0] = __float_as_uint(As[(kloc+c  )*P_ASTR + row    ]);
                a[mt][1] = __float_as_uint(As[(kloc+c  )*P_ASTR + row + 8]);
                a[mt][2] = __float_as_uint(As[(kloc+c+4)*P_ASTR + row    ]);
                a[mt][3] = __float_as_uint(As[(kloc+c+4)*P_ASTR + row + 8]);
            }
#pragma unroll
            for (int nt = 0; nt < 5; nt++) {
                int oc = woc + nt*8 + r;
                bf[nt][0] = __float_as_uint(Bs[oc*P_BSTR + kk + c    ]);
                bf[nt][1] = __float_as_uint(Bs[oc*P_BSTR + kk + c + 4]);
            }
#pragma unroll
            for (int mt = 0; mt < 4; mt++)
#pragma unroll
                for (int nt = 0; nt < 5; nt++)
                    mma16n8k8(acc[mt][nt], a[mt], bf[nt]);
        }
        __syncthreads();                       // reads of raw[s]/As done

        if (ck + 2 < 4) {
            int k0n = (ck + 2) * 32;
            if (tid == 0) {
                if (s == 0) MBAR_EXPECT_TX(mb0, txA);
                else        MBAR_EXPECT_TX(mb1, txA);
            }
            if (tid < 128) {
                int rr = tid >> 5, cc = tid & 31;
                int gy = y0 - 1 + rr;
                if ((unsigned)gy < HH)
                    bulk_g2s(rawb + (uint32_t)((s*P_RAWH +
                                 (rr*32 + cc)*P_RSTH + 8)*2),
                             cfb + (size_t)(k0n + cc)*HWP + gy*WW, 256,
                             (s == 0) ? mb0 : mb1);
            }
        }
    }

    // epilogue: transpose via smem -> coalesced fp32 stores
    float* sOut = dsm;                          // [80][256]
#pragma unroll
    for (int mt = 0; mt < 4; mt++) {
        int row = wpx + mt*16 + r;
#pragma unroll
        for (int nt = 0; nt < 5; nt++) {
            int col = woc + nt*8 + c*2;
            sOut[(col  )*256 + row    ] = acc[mt][nt][0];
            sOut[(col+1)*256 + row    ] = acc[mt][nt][1];
            sOut[(col  )*256 + row + 8] = acc[mt][nt][2];
            sOut[(col+1)*256 + row + 8] = acc[mt][nt][3];
        }
    }
    __syncthreads();

    size_t ob = (size_t)b * OUTC * HWP + (size_t)y0 * WW;
    for (int i = tid; i < CO*64; i += 256) {
        int oc = i >> 6, p4 = (i & 63) * 4;
        float bi = sb[oc];
        float4 v = *(float4*)&sOut[oc*256 + p4];
        v.x = fmaxf(v.x + bi, 0.f); v.y = fmaxf(v.y + bi, 0.f);
        v.z = fmaxf(v.z + bi, 0.f); v.w = fmaxf(v.w + bi, 0.f);
        *(float4*)&out[ob + (size_t)oc*HWP + p4] = v;
    }
}

// ---------------------------------------------------------------------------
extern "C" void kernel_launch(void* const* d_in, const int* in_sizes, int n_in,
                              void* d_out, int out_size) {
    const float* flow = (const float*)d_in[0];
    const float* corr = (const float*)d_in[1];
    const float* Wc1  = (const float*)d_in[2];
    const float* bc1  = (const float*)d_in[3];
    const float* bf1  = (const float*)d_in[5];
    const float* bf2  = (const float*)d_in[7];
    const float* bp   = (const float*)d_in[10];
    float* out = (float*)d_out;

    const int CONV_SMEM = (C1_AS_F + C1_BS_F + 4) * 4;        // ~155.2 KB
    const int PWDW_SMEM = (P_MB_OFF + 4) * 4;                 // ~156.2 KB
    cudaFuncSetAttribute(convflo_kernel,
                         cudaFuncAttributeMaxDynamicSharedMemorySize, CONV_SMEM);
    cudaFuncSetAttribute(pwdw_kernel,
                         cudaFuncAttributeMaxDynamicSharedMemorySize, PWDW_SMEM);

    quant_kernel<<<5, 1024>>>(Wc1, (const float*)d_in[4], (const float*)d_in[6],
                              (const float*)d_in[8], (const float*)d_in[9]);
    convflo_kernel<<<dim3(48 + HWP/512, BB), 512, CONV_SMEM>>>(
        corr, bc1, flow, bf1, bf2, out);
    pwdw_kernel<<<dim3(HH/2, BB), 256, PWDW_SMEM>>>(bp, out);
}

// round 10
// speedup vs baseline: 3.5096x; 1.0374x over previous
#include <cuda_runtime.h>
#include <cuda_fp16.h>
#include <cstdint>

#define BB 16
#define HH 96
#define WW 128
#define HWP 12288
#define CP 196
#define C1 96
#define CF1 64
#define CF2 32
#define CM 128
#define CO 80
#define OUTC 82

// ---- globals (no allocation allowed) --------------------------------------
__device__ __align__(16) __half g_corflo[(size_t)BB*CM*HWP];  // fp16 cor_flo
__device__ __align__(16) float g_Wc1q[C1*CP];   // fake-quant + tf32-rounded
__device__ __align__(16) float g_Wf1[CF1*2];
__device__ __align__(16) float g_Wf2[CF2*CF1];
__device__ __align__(16) float g_Wd[CM*9];
__device__ __align__(16) float g_Wpq[CO*CM];    // fake-quant + tf32-rounded

__device__ __forceinline__ float totf32(float x) {
    float r; asm("cvt.rna.tf32.f32 %0, %1;" : "=f"(r) : "f"(x)); return r;
}
__device__ __forceinline__ void mma16n8k8(float* d, const uint32_t* a,
                                          const uint32_t* b) {
    asm volatile(
        "mma.sync.aligned.m16n8k8.row.col.f32.tf32.tf32.f32 "
        "{%0,%1,%2,%3}, {%4,%5,%6,%7}, {%8,%9}, {%0,%1,%2,%3};"
        : "+f"(d[0]), "+f"(d[1]), "+f"(d[2]), "+f"(d[3])
        : "r"(a[0]), "r"(a[1]), "r"(a[2]), "r"(a[3]), "r"(b[0]), "r"(b[1]));
}
__device__ __forceinline__ uint32_t smem_u32(const void* p) {
    uint32_t a;
    asm("{ .reg .u64 t; cvta.to.shared.u64 t, %1; cvt.u32.u64 %0, t; }"
        : "=r"(a) : "l"(p));
    return a;
}
__device__ __forceinline__ void bulk_g2s(uint32_t dst, const void* src,
                                         uint32_t bytes, uint32_t mbar) {
    asm volatile(
        "cp.async.bulk.shared::cluster.global.mbarrier::complete_tx::bytes "
        "[%0], [%1], %2, [%3];"
        :: "r"(dst), "l"(src), "r"(bytes), "r"(mbar) : "memory");
}
#define MBAR_INIT(mb, c) \
    asm volatile("mbarrier.init.shared.b64 [%0], %1;" :: "r"(mb), "r"(c) : "memory")
#define MBAR_EXPECT_TX(mb, bytes) \
    asm volatile("mbarrier.arrive.expect_tx.shared.b64 _, [%0], %1;" \
                 :: "r"(mb), "r"((uint32_t)(bytes)) : "memory")
#define MBAR_WAIT(mb, ph) do {                                               \
    asm volatile("{\n\t.reg .pred P1;\n\t"                                   \
        "WL%=:\n\tmbarrier.try_wait.parity.acquire.cta.shared::cta.b64 "     \
        "P1, [%0], %1, 0x989680;\n\t"                                        \
        "@P1 bra.uni WD%=;\n\tbra.uni WL%=;\n\tWD%=:\n\t}"                   \
        :: "r"(mb), "r"((uint32_t)(ph)) : "memory"); } while (0)

// ---------------------------------------------------------------------------
// Per-tensor symmetric int8 fake-quant; GEMM weights tf32-pre-rounded.
// ---------------------------------------------------------------------------
__global__ void quant_kernel(const float* __restrict__ Wc1,
                             const float* __restrict__ Wf1,
                             const float* __restrict__ Wf2,
                             const float* __restrict__ Wd,
                             const float* __restrict__ Wp) {
    __shared__ float smax[1024];
    __shared__ float sscale;
    int t = blockIdx.x;
    const float* src; int n;
    if (t == 0)      { src = Wc1; n = C1*CP;   }
    else if (t == 1) { src = Wf1; n = CF1*2;   }
    else if (t == 2) { src = Wf2; n = CF2*CF1; }
    else if (t == 3) { src = Wd;  n = CM*9;    }
    else             { src = Wp;  n = CO*CM;   }

    float m = 0.f;
    for (int i = threadIdx.x; i < n; i += 1024) m = fmaxf(m, fabsf(src[i]));
    smax[threadIdx.x] = m;
    __syncthreads();
    for (int s = 512; s > 0; s >>= 1) {
        if (threadIdx.x < s)
            smax[threadIdx.x] = fmaxf(smax[threadIdx.x], smax[threadIdx.x + s]);
        __syncthreads();
    }
    if (threadIdx.x == 0) sscale = fmaxf(smax[0], 1e-8f) / 127.f;
    __syncthreads();
    float sc = sscale, inv = 1.f / sc;

    for (int i = threadIdx.x; i < n; i += 1024) {
        float q = rintf(src[i] * inv);
        q = fminf(fmaxf(q, -127.f), 127.f) * sc;
        if (t == 0)      g_Wc1q[i] = totf32(q);
        else if (t == 1) g_Wf1[i] = q;
        else if (t == 2) g_Wf2[i] = q;
        else if (t == 3) g_Wd[i]  = q;
        else             g_Wpq[i] = totf32(q);
    }
}

// ---------------------------------------------------------------------------
// convflo: blocks x<48 = conv1 (256px x 96oc tf32 GEMM, cp.async.bulk
// double-buffered A, resident B); blocks x>=48 = flow MLP.
// A fragments feed raw fp32 bits to mma.tf32 (HW truncation) -> no cvt chain.
// ---------------------------------------------------------------------------
#define C1_ASTR 264
#define C1_BSTR 228
#define C1_AS_F (2*32*C1_ASTR)          // 16896 floats
#define C1_BS_F (C1*C1_BSTR)            // 21888 floats

__global__ void __launch_bounds__(512)
convflo_kernel(const float* __restrict__ corr, const float* __restrict__ bc1,
               const float* __restrict__ flow, const float* __restrict__ bf1,
               const float* __restrict__ bf2, float* __restrict__ out) {
    extern __shared__ __align__(16) float dsm[];
    int tid = threadIdx.x;
    int b   = blockIdx.y;

    if (blockIdx.x >= 48) {
        // ---------------- flo part ----------------
        float* sW1 = dsm;
        float* sb1 = dsm + 128;
        float* sW2 = dsm + 192;
        float* sb2 = dsm + 2240;
        for (int i = tid; i < CF1*2;   i += 512) sW1[i] = g_Wf1[i];
        for (int i = tid; i < CF1;     i += 512) sb1[i] = bf1[i];
        for (int i = tid; i < CF2*CF1; i += 512) sW2[i] = g_Wf2[i];
        for (int i = tid; i < CF2;     i += 512) sb2[i] = bf2[i];
        __syncthreads();

        int px = (blockIdx.x - 48) * 512 + tid;
        float f0 = flow[((size_t)b*2 + 0)*HWP + px];
        float f1 = flow[((size_t)b*2 + 1)*HWP + px];

        float hid[CF1];
#pragma unroll
        for (int h = 0; h < CF1; h++)
            hid[h] = fmaxf(f0*sW1[h*2] + f1*sW1[h*2+1] + sb1[h], 0.f);
#pragma unroll
        for (int o = 0; o < CF2; o++) {
            float a = sb2[o];
#pragma unroll
            for (int h = 0; h < CF1; h++) a += hid[h] * sW2[o*CF1 + h];
            g_corflo[((size_t)(b*CM + C1 + o))*HWP + px] =
                __float2half(fmaxf(a, 0.f));
        }
        out[((size_t)(b*OUTC + 80))*HWP + px] = f0;
        out[((size_t)(b*OUTC + 81))*HWP + px] = f1;
        return;
    }

    // ---------------- conv1 ----------------
    float* As = dsm;                     // [2][32][264]
    float* Bs = dsm + C1_AS_F;           // [96][228]
    unsigned long long* mb = (unsigned long long*)(dsm + C1_AS_F + C1_BS_F);
    uint32_t asb = smem_u32(As), bsb = smem_u32(Bs);
    uint32_t mb0 = smem_u32(&mb[0]), mb1 = smem_u32(&mb[1]);

    int wid = tid >> 5, lane = tid & 31;
    int r = lane >> 2, c = lane & 3;
    int wpx = (wid & 3) * 64;
    int woc = (wid >> 2) * 24;
    int px0 = blockIdx.x * 256;
    const float* Xb = corr + (size_t)b * CP * HWP + px0;

    if (tid == 0) { MBAR_INIT(mb0, 1); MBAR_INIT(mb1, 1); }
    for (int i = tid; i < C1*8; i += 512) {
        int oc = i >> 3, j = i & 7;
        *(float4*)&Bs[oc*C1_BSTR + 196 + j*4] = make_float4(0.f,0.f,0.f,0.f);
    }
    float bias[3][2];
#pragma unroll
    for (int nt = 0; nt < 3; nt++) {
        bias[nt][0] = bc1[woc + nt*8 + c*2];
        bias[nt][1] = bc1[woc + nt*8 + c*2 + 1];
    }
    __syncthreads();

    if (tid == 0) {
        MBAR_EXPECT_TX(mb0, 32*1024 + C1*784);
        MBAR_EXPECT_TX(mb1, 32*1024);
    }
    if (tid < 32) {
        bulk_g2s(asb + (uint32_t)(tid*C1_ASTR)*4, Xb + (size_t)tid*HWP,
                 1024, mb0);
    } else if (tid < 128) {
        int oc = tid - 32;
        bulk_g2s(bsb + (uint32_t)(oc*C1_BSTR)*4, g_Wc1q + oc*CP, 784, mb0);
    } else if (tid < 160) {
        int t2 = tid - 128;
        bulk_g2s(asb + (uint32_t)((32 + t2)*C1_ASTR)*4,
                 Xb + (size_t)(32 + t2)*HWP, 1024, mb1);
    }

    float acc[4][3][4];
#pragma unroll
    for (int mt = 0; mt < 4; mt++)
#pragma unroll
        for (int nt = 0; nt < 3; nt++)
#pragma unroll
            for (int i = 0; i < 4; i++) acc[mt][nt][i] = 0.f;

    int ph0 = 0, ph1 = 0;
    for (int ch = 0; ch < 7; ch++) {
        int s = ch & 1;
        if (s == 0) { MBAR_WAIT(mb0, ph0); ph0 ^= 1; }
        else        { MBAR_WAIT(mb1, ph1); ph1 ^= 1; }
        const float* Ac = As + s * 32 * C1_ASTR;

#pragma unroll
        for (int ks = 0; ks < 4; ks++) {
            int kloc = ks * 8;
            int kk = ch * 32 + kloc;
            if (kk >= CP) break;
            uint32_t a[4][4], bf[3][2];
#pragma unroll
            for (int mt = 0; mt < 4; mt++) {
                int row = wpx + mt*16 + r;
                // raw fp32 bits -> mma.tf32 truncates (no cvt in chain)
                a[mt][0] = __float_as_uint(Ac[(kloc+c  )*C1_ASTR + row    ]);
                a[mt][1] = __float_as_uint(Ac[(kloc+c  )*C1_ASTR + row + 8]);
                a[mt][2] = __float_as_uint(Ac[(kloc+c+4)*C1_ASTR + row    ]);
                a[mt][3] = __float_as_uint(Ac[(kloc+c+4)*C1_ASTR + row + 8]);
            }
#pragma unroll
            for (int nt = 0; nt < 3; nt++) {
                int oc = woc + nt*8 + r;
                bf[nt][0] = __float_as_uint(Bs[oc*C1_BSTR + kk + c    ]);
                bf[nt][1] = __float_as_uint(Bs[oc*C1_BSTR + kk + c + 4]);
            }
#pragma unroll
            for (int mt = 0; mt < 4; mt++)
#pragma unroll
                for (int nt = 0; nt < 3; nt++)
                    mma16n8k8(acc[mt][nt], a[mt], bf[nt]);
        }
        __syncthreads();

        int nc = ch + 2;
        if (nc < 7) {
            int k0 = nc * 32;
            int nr = CP - k0; if (nr > 32) nr = 32;
            if (tid == 0) {
                if (s == 0) MBAR_EXPECT_TX(mb0, nr*1024);
                else        MBAR_EXPECT_TX(mb1, nr*1024);
            }
            if (tid < nr)
                bulk_g2s(asb + (uint32_t)((s*32 + tid)*C1_ASTR)*4,
                         Xb + (size_t)(k0 + tid)*HWP, 1024,
                         (s == 0) ? mb0 : mb1);
        }
    }

    __half* cf = g_corflo + (size_t)b * CM * HWP + px0;
#pragma unroll
    for (int mt = 0; mt < 4; mt++) {
        int row = wpx + mt*16 + r;
#pragma unroll
        for (int nt = 0; nt < 3; nt++) {
            int col = woc + nt*8 + c*2;
            cf[(size_t)col*HWP + row] =
                __float2half(fmaxf(acc[mt][nt][0] + bias[nt][0], 0.f));
            cf[(size_t)(col+1)*HWP + row] =
                __float2half(fmaxf(acc[mt][nt][1] + bias[nt][1], 0.f));
            cf[(size_t)col*HWP + row + 8] =
                __float2half(fmaxf(acc[mt][nt][2] + bias[nt][0], 0.f));
            cf[(size_t)(col+1)*HWP + row + 8] =
                __float2half(fmaxf(acc[mt][nt][3] + bias[nt][1], 0.f));
        }
    }
}

// ---------------------------------------------------------------------------
// pwdw: fused depthwise-3x3 + pointwise 128->80 tf32 GEMM, 2 rows/block.
// NOW 512 threads (8 px-warps x 2 oc-warps) -> 4 warps/SMSP.
// ---------------------------------------------------------------------------
#define P_RSTH 144
#define P_RAWH (4*32*P_RSTH)
#define P_ASTR 264
#define P_BSTR 132
#define P_AS_OFF 18432
#define P_BS_OFF (P_AS_OFF + 32*P_ASTR)
#define P_WD_OFF (P_BS_OFF + CO*P_BSTR)
#define P_SB_OFF (P_WD_OFF + CM*12)
#define P_MB_OFF (P_SB_OFF + CO)

__global__ void __launch_bounds__(512)
pwdw_kernel(const float* __restrict__ bp, float* __restrict__ out) {
    extern __shared__ __align__(16) float dsm[];
    __half* raw = (__half*)dsm;
    float* As  = dsm + P_AS_OFF;
    float* Bs  = dsm + P_BS_OFF;
    float* wds = dsm + P_WD_OFF;
    float* sb  = dsm + P_SB_OFF;
    unsigned long long* mb = (unsigned long long*)(dsm + P_MB_OFF);

    int tid = threadIdx.x;
    int wid = tid >> 5, lane = tid & 31;
    int r = lane >> 2, c = lane & 3;
    int wpx = (wid & 7) * 32;            // 8 px-warps x 32 px (2 m-tiles)
    int woc = (wid >> 3) * 40;           // 2 oc-warps x 40 oc (5 n-tiles)
    int y0 = blockIdx.x * 2;
    int b  = blockIdx.y;
    uint32_t rawb = smem_u32(raw);
    uint32_t mb0 = smem_u32(&mb[0]), mb1 = smem_u32(&mb[1]);
    const __half* cfb = g_corflo + (size_t)b * CM * HWP;

    if (tid == 0) { MBAR_INIT(mb0, 1); MBAR_INIT(mb1, 1); }
    for (int i = tid; i < CO; i += 512) sb[i] = bp[i];
    for (int i = tid; i < CM*9; i += 512) wds[(i/9)*12 + (i%9)] = g_Wd[i];
    for (int i = tid; i < 2*128; i += 512) {
        int o = (i >> 7) * P_RAWH + (i & 127) * P_RSTH;
        raw[o + 7] = __float2half(0.f);
        raw[o + 136] = __float2half(0.f);
    }
    int rinv = (y0 == 0) ? 0 : ((y0 == HH - 2) ? 3 : -1);
    if (rinv >= 0) {
        uint32_t* rz = (uint32_t*)raw;
        for (int i = tid; i < 2*32*72; i += 512) {
            int bu = i / (32*72), rem = i % (32*72);
            int cc = rem / 72, hw = rem % 72;
            rz[(bu*P_RAWH + (rinv*32 + cc)*P_RSTH)/2 + hw] = 0;
        }
    }
    int nv = 4 - (y0 == 0) - (y0 == HH - 2);
    uint32_t txA = (uint32_t)nv * 32 * 256;
    __syncthreads();

    if (tid == 0) {
        MBAR_EXPECT_TX(mb0, txA + CO*512);
        MBAR_EXPECT_TX(mb1, txA);
    }
    if (tid < 128) {
        int rr = tid >> 5, cc = tid & 31;
        int gy = y0 - 1 + rr;
        if ((unsigned)gy < HH) {
            bulk_g2s(rawb + (uint32_t)(((rr*32 + cc)*P_RSTH + 8)*2),
                     cfb + (size_t)cc*HWP + gy*WW, 256, mb0);
            bulk_g2s(rawb + (uint32_t)((P_RAWH + (rr*32 + cc)*P_RSTH + 8)*2),
                     cfb + (size_t)(32 + cc)*HWP + gy*WW, 256, mb1);
        }
    } else if (tid < 208) {
        int oc = tid - 128;
        bulk_g2s(smem_u32(Bs) + (uint32_t)(oc*P_BSTR)*4,
                 g_Wpq + oc*CM, 512, mb0);
    }

    float acc[2][5][4];
#pragma unroll
    for (int mt = 0; mt < 2; mt++)
#pragma unroll
        for (int nt = 0; nt < 5; nt++)
#pragma unroll
            for (int i = 0; i < 4; i++) acc[mt][nt][i] = 0.f;

    int ph0 = 0, ph1 = 0;
    for (int ck = 0; ck < 4; ck++) {
        int s = ck & 1;
        if (s == 0) { MBAR_WAIT(mb0, ph0); ph0 ^= 1; }
        else        { MBAR_WAIT(mb1, ph1); ph1 ^= 1; }

        const __half* rb = raw + s * P_RAWH;
        const float* wb = wds + ck * 32 * 12;
#pragma unroll
        for (int v = 0; v < 4; v++) {
            int i = tid + 512*v;
            int cc = i >> 6, q = i & 63;
            int yy = q >> 5, x = (q & 31) * 4;
            float4 a4 = make_float4(0.f, 0.f, 0.f, 0.f);
#pragma unroll
            for (int rr = 0; rr < 3; rr++) {
                const __half* rp = rb + ((yy + rr)*32 + cc)*P_RSTH + 8 + x;
                float2 f01 = __half22float2(*(const __half2*)rp);
                float2 f23 = __half22float2(*(const __half2*)(rp + 2));
                float xl = __half2float(rp[-1]);
                float xr = __half2float(rp[4]);
                const float* w = wb + cc*12 + rr*3;
                a4.x += w[0]*xl    + w[1]*f01.x + w[2]*f01.y;
                a4.y += w[0]*f01.x + w[1]*f01.y + w[2]*f23.x;
                a4.z += w[0]*f01.y + w[1]*f23.x + w[2]*f23.y;
                a4.w += w[0]*f23.x + w[1]*f23.y + w[2]*xr;
            }
            *(float4*)&As[cc*P_ASTR + yy*128 + x] =
                make_float4(totf32(a4.x), totf32(a4.y),
                            totf32(a4.z), totf32(a4.w));
        }
        __syncthreads();

#pragma unroll
        for (int ks = 0; ks < 4; ks++) {
            int kloc = ks * 8;
            int kk = ck * 32 + kloc;
            uint32_t a[2][4], bf[5][2];
#pragma unroll
            for (int mt = 0; mt < 2; mt++) {
                int row = wpx + mt*16 + r;
                a[mt][0] = __float_as_uint(As[(kloc+c  )*P_ASTR + row    ]);
                a[mt][1] = __float_as_uint(As[(kloc+c  )*P_ASTR + row + 8]);
                a[mt][2] = __float_as_uint(As[(kloc+c+4)*P_ASTR + row    ]);
                a[mt][3] = __float_as_uint(As[(kloc+c+4)*P_ASTR + row + 8]);
            }
#pragma unroll
            for (int nt = 0; nt < 5; nt++) {
                int oc = woc + nt*8 + r;
                bf[nt][0] = __float_as_uint(Bs[oc*P_BSTR + kk + c    ]);
                bf[nt][1] = __float_as_uint(Bs[oc*P_BSTR + kk + c + 4]);
            }
#pragma unroll
            for (int mt = 0; mt < 2; mt++)
#pragma unroll
                for (int nt = 0; nt < 5; nt++)
                    mma16n8k8(acc[mt][nt], a[mt], bf[nt]);
        }
        __syncthreads();

        if (ck + 2 < 4) {
            int k0n = (ck + 2) * 32;
            if (tid == 0) {
                if (s == 0) MBAR_EXPECT_TX(mb0, txA);
                else        MBAR_EXPECT_TX(mb1, txA);
            }
            if (tid < 128) {
                int rr = tid >> 5, cc = tid & 31;
                int gy = y0 - 1 + rr;
                if ((unsigned)gy < HH)
                    bulk_g2s(rawb + (uint32_t)((s*P_RAWH +
                                 (rr*32 + cc)*P_RSTH + 8)*2),
                             cfb + (size_t)(k0n + cc)*HWP + gy*WW, 256,
                             (s == 0) ? mb0 : mb1);
            }
        }
    }

    // epilogue: transpose via smem -> coalesced fp32 stores
    float* sOut = dsm;                          // [80][256]
#pragma unroll
    for (int mt = 0; mt < 2; mt++) {
        int row = wpx + mt*16 + r;
#pragma unroll
        for (int nt = 0; nt < 5; nt++) {
            int col = woc + nt*8 + c*2;
            sOut[(col  )*256 + row    ] = acc[mt][nt][0];
            sOut[(col+1)*256 + row    ] = acc[mt][nt][1];
            sOut[(col  )*256 + row + 8] = acc[mt][nt][2];
            sOut[(col+1)*256 + row + 8] = acc[mt][nt][3];
        }
    }
    __syncthreads();

    size_t ob = (size_t)b * OUTC * HWP + (size_t)y0 * WW;
    for (int i = tid; i < CO*64; i += 512) {
        int oc = i >> 6, p4 = (i & 63) * 4;
        float bi = sb[oc];
        float4 v = *(float4*)&sOut[oc*256 + p4];
        v.x = fmaxf(v.x + bi, 0.f); v.y = fmaxf(v.y + bi, 0.f);
        v.z = fmaxf(v.z + bi, 0.f); v.w = fmaxf(v.w + bi, 0.f);
        *(float4*)&out[ob + (size_t)oc*HWP + p4] = v;
    }
}

// ---------------------------------------------------------------------------
extern "C" void kernel_launch(void* const* d_in, const int* in_sizes, int n_in,
                              void* d_out, int out_size) {
    const float* flow = (const float*)d_in[0];
    const float* corr = (const float*)d_in[1];
    const float* Wc1  = (const float*)d_in[2];
    const float* bc1  = (const float*)d_in[3];
    const float* bf1  = (const float*)d_in[5];
    const float* bf2  = (const float*)d_in[7];
    const float* bp   = (const float*)d_in[10];
    float* out = (float*)d_out;

    const int CONV_SMEM = (C1_AS_F + C1_BS_F + 4) * 4;
    const int PWDW_SMEM = (P_MB_OFF + 4) * 4;
    cudaFuncSetAttribute(convflo_kernel,
                         cudaFuncAttributeMaxDynamicSharedMemorySize, CONV_SMEM);
    cudaFuncSetAttribute(pwdw_kernel,
                         cudaFuncAttributeMaxDynamicSharedMemorySize, PWDW_SMEM);

    quant_kernel<<<5, 1024>>>(Wc1, (const float*)d_in[4], (const float*)d_in[6],
                              (const float*)d_in[8], (const float*)d_in[9]);
    convflo_kernel<<<dim3(48 + HWP/512, BB), 512, CONV_SMEM>>>(
        corr, bc1, flow, bf1, bf2, out);
    pwdw_kernel<<<dim3(HH/2, BB), 512, PWDW_SMEM>>>(bp, out);
}